// round 2
// baseline (speedup 1.0000x reference)
#include <cuda_runtime.h>
#include <cstdint>
#include <math.h>

// ---------------- static device scratch ----------------
#define BMAX 2048
__device__ float g_buf0[BMAX * 10 * 4 * 26 * 26];   // ~221 MB
__device__ float g_buf1[BMAX * 10 * 4 * 24 * 24];   // ~189 MB
__device__ float g_att [BMAX * 4 * 26 * 26];        // att maps / gated L1 input
__device__ float g_pool[BMAX * 2 * 4 * 26 * 26];    // pooled (mean,max) for attention

__device__ double g_sum[60], g_sq[60];
__device__ float  g_scale[60], g_shift[60];

// rotated weights
__device__ float g_wl[4 * 3 * 3 * 10];              // lifting [r][u][v][o]
__device__ float g_wc[5 * 4 * 10 * 4 * 3 * 3 * 10]; // GG convs 2..6 [l][r][i][s][u][v][o]
__device__ float g_wc7[4 * 10 * 4 * 4 * 4 * 10];    // GG conv 7 [r][i][s][u][v][o]
__device__ float g_wa1[49];                         // L1 att (mean+max weights summed)
__device__ float g_wa[6 * 4 * 2 * 4 * 7 * 7];       // GG att 2..7 [l][r][i][s][u][v]

__device__ __forceinline__ void rotmap(int r, int u, int v, int K, int& su, int& sv) {
    switch (r & 3) {
        case 0: su = u;         sv = v;         break;
        case 1: su = v;         sv = K - 1 - u; break;
        case 2: su = K - 1 - u; sv = K - 1 - v; break;
        default: su = K - 1 - v; sv = u;        break;
    }
}

__device__ __forceinline__ float warpsum(float v) {
    for (int o = 16; o > 0; o >>= 1) v += __shfl_down_sync(0xffffffffu, v, o);
    return v;
}

// ---------------- prep: rotate weights, zero stats ----------------
__global__ void prepk(const float* c1, const float* c2, const float* c3, const float* c4,
                      const float* c5, const float* c6, const float* c7,
                      const float* a1, const float* a2, const float* a3, const float* a4,
                      const float* a5, const float* a6, const float* a7) {
    int tid = blockIdx.x * blockDim.x + threadIdx.x;
    int nth = gridDim.x * blockDim.x;
    const float* cws[5] = {c2, c3, c4, c5, c6};
    const float* aws[6] = {a2, a3, a4, a5, a6, a7};

    for (int idx = tid; idx < 360; idx += nth) {
        int o = idx % 10, t = idx / 10;
        int v = t % 3; t /= 3; int u = t % 3; int r = t / 3;
        int su, sv; rotmap(r, u, v, 3, su, sv);
        g_wl[idx] = c1[o * 9 + su * 3 + sv];
    }
    for (int idx = tid; idx < 5 * 14400; idx += nth) {
        int o = idx % 10; int t = idx / 10;
        int v = t % 3; t /= 3; int u = t % 3; t /= 3;
        int s = t & 3; t >>= 2; int i = t % 10; t /= 10;
        int r = t & 3; int l = t >> 2;
        int sp = (s - r) & 3; int su, sv; rotmap(r, u, v, 3, su, sv);
        g_wc[idx] = cws[l][((o * 10 + i) * 4 + sp) * 9 + su * 3 + sv];
    }
    for (int idx = tid; idx < 25600; idx += nth) {
        int o = idx % 10; int t = idx / 10;
        int v = t & 3; t >>= 2; int u = t & 3; t >>= 2;
        int s = t & 3; t >>= 2; int i = t % 10; int r = t / 10;
        int sp = (s - r) & 3; int su, sv; rotmap(r, u, v, 4, su, sv);
        g_wc7[idx] = c7[((o * 10 + i) * 4 + sp) * 16 + su * 4 + sv];
    }
    for (int idx = tid; idx < 49; idx += nth) g_wa1[idx] = a1[idx] + a1[49 + idx];
    for (int idx = tid; idx < 6 * 1568; idx += nth) {
        int v = idx % 7; int t = idx / 7;
        int u = t % 7; t /= 7; int s = t & 3; t >>= 2;
        int i = t & 1; t >>= 1; int r = t & 3; int l = t >> 2;
        int sp = (s - r) & 3; int su, sv; rotmap(r, u, v, 7, su, sv);
        g_wa[idx] = aws[l][(i * 4 + sp) * 49 + su * 7 + sv];
    }
    for (int idx = tid; idx < 60; idx += nth) { g_sum[idx] = 0.0; g_sq[idx] = 0.0; }
}

// ---------------- layer 1 attention + gating ----------------
__global__ void __launch_bounds__(256) att1k(const float* __restrict__ x) {
    __shared__ float xt[34 * 34];
    __shared__ float w[49];
    int b = blockIdx.x, tid = threadIdx.x;
    for (int i = tid; i < 34 * 34; i += 256) xt[i] = 0.f;
    for (int i = tid; i < 49; i += 256) w[i] = g_wa1[i];
    __syncthreads();
    for (int i = tid; i < 784; i += 256) {
        int y = i / 28, xx = i % 28;
        xt[(y + 3) * 34 + xx + 3] = x[(size_t)b * 784 + i];
    }
    __syncthreads();
    for (int p = tid; p < 784; p += 256) {
        int y = p / 28, xx = p % 28;
        float acc = 0.f;
#pragma unroll
        for (int u = 0; u < 7; u++)
#pragma unroll
            for (int v = 0; v < 7; v++)
                acc = fmaf(xt[(y + u) * 34 + xx + v], w[u * 7 + v], acc);
        float xv = xt[(y + 3) * 34 + xx + 3];
        g_att[(size_t)b * 784 + p] = xv * (1.f / (1.f + expf(-acc)));
    }
}

// ---------------- layer 1 lifting conv (valid 3x3, 4 rotations) ----------------
__global__ void __launch_bounds__(256) conv1k() {
    __shared__ float sx[784];
    __shared__ float sw[360];
    __shared__ float bsum[10], bsq[10];
    int b = blockIdx.x, tid = threadIdx.x;
    for (int i = tid; i < 784; i += 256) sx[i] = g_att[(size_t)b * 784 + i];
    for (int i = tid; i < 360; i += 256) sw[i] = g_wl[i];
    if (tid < 10) { bsum[tid] = 0.f; bsq[tid] = 0.f; }
    __syncthreads();
    float ts[10], tq[10];
#pragma unroll
    for (int o = 0; o < 10; o++) { ts[o] = 0.f; tq[o] = 0.f; }
    for (int r = 0; r < 4; r++) {
        for (int pp = tid; pp < 338; pp += 256) {
            int y = pp / 13, x0 = (pp % 13) * 2;
            float a0[10], a1[10];
#pragma unroll
            for (int o = 0; o < 10; o++) { a0[o] = 0.f; a1[o] = 0.f; }
#pragma unroll
            for (int u = 0; u < 3; u++)
#pragma unroll
                for (int v = 0; v < 3; v++) {
                    float xv0 = sx[(y + u) * 28 + x0 + v];
                    float xv1 = sx[(y + u) * 28 + x0 + v + 1];
                    const float* wp = &sw[((r * 3 + u) * 3 + v) * 10];
#pragma unroll
                    for (int o = 0; o < 10; o++) {
                        a0[o] = fmaf(xv0, wp[o], a0[o]);
                        a1[o] = fmaf(xv1, wp[o], a1[o]);
                    }
                }
#pragma unroll
            for (int o = 0; o < 10; o++) {
                size_t off = ((((size_t)b * 10 + o) * 4 + r) * 26 + y) * 26 + x0;
                g_buf0[off] = a0[o]; g_buf0[off + 1] = a1[o];
                ts[o] += a0[o] + a1[o];
                tq[o] += a0[o] * a0[o] + a1[o] * a1[o];
            }
        }
    }
#pragma unroll
    for (int o = 0; o < 10; o++) {
        float s = warpsum(ts[o]);
        float q = warpsum(tq[o]);
        if ((tid & 31) == 0) { atomicAdd(&bsum[o], s); atomicAdd(&bsq[o], q); }
    }
    __syncthreads();
    if (tid < 10) {
        atomicAdd(&g_sum[tid], (double)bsum[tid]);
        atomicAdd(&g_sq[tid], (double)bsq[tid]);
    }
}

// ---------------- pooled (mean,max over channels) for attention ----------------
template <int HIN>
__global__ void poolk(const float* __restrict__ in, int B) {
    const int H2 = HIN * HIN;
    int total = B * 4 * H2;
    for (int idx = blockIdx.x * blockDim.x + threadIdx.x; idx < total;
         idx += gridDim.x * blockDim.x) {
        int pos = idx % H2;
        int s = (idx / H2) & 3;
        int b = idx / (4 * H2);
        const float* p = in + ((size_t)b * 40 + s) * H2 + pos;
        float sum = 0.f, mx = -3.4e38f;
#pragma unroll
        for (int c = 0; c < 10; c++) {
            float v = p[(size_t)c * 4 * H2];
            sum += v; mx = fmaxf(mx, v);
        }
        g_pool[((size_t)b * 8 + s) * H2 + pos]     = sum / 10.0f;
        g_pool[((size_t)b * 8 + 4 + s) * H2 + pos] = mx;
    }
}

// ---------------- GG attention conv (7x7 SAME) + sigmoid ----------------
template <int HIN>
__global__ void __launch_bounds__(256) attk(int layer) {
    const int PW = HIN + 6, H2 = HIN * HIN;
    __shared__ float pt[2 * 4 * PW * PW];
    __shared__ float wa[392];
    int b = blockIdx.x >> 2, r = blockIdx.x & 3;
    int tid = threadIdx.x;
    const float* wa_l = &g_wa[layer * 1568];
    for (int i = tid; i < 2 * 4 * PW * PW; i += 256) pt[i] = 0.f;
    for (int i = tid; i < 392; i += 256) wa[i] = wa_l[r * 392 + i];
    __syncthreads();
    const float* pb = g_pool + (size_t)b * 8 * H2;
    for (int idx = tid; idx < 8 * H2; idx += 256) {
        int xx = idx % HIN;
        int y = (idx / HIN) % HIN;
        int js = idx / H2;   // [j][s] combined
        pt[(js * PW + y + 3) * PW + xx + 3] = pb[idx];
    }
    __syncthreads();
    for (int p = tid; p < H2; p += 256) {
        int y = p / HIN, xx = p % HIN;
        float acc = 0.f;
#pragma unroll
        for (int js = 0; js < 8; js++) {
            const float* ptb = &pt[(js * PW + y) * PW + xx];
            const float* wb = &wa[js * 49];
#pragma unroll
            for (int u = 0; u < 7; u++)
#pragma unroll
                for (int v = 0; v < 7; v++)
                    acc = fmaf(ptb[u * PW + v], wb[u * 7 + v], acc);
        }
        g_att[((size_t)b * 4 + r) * H2 + p] = 1.f / (1.f + expf(-acc));
    }
}

// ---------------- main GG conv (valid 3x3), gated input, BN-stat accumulation ----
template <int HIN, int NT>
__global__ void __launch_bounds__(NT) convgg(const float* __restrict__ in,
                                             float* __restrict__ out,
                                             int layer, int statsIdx) {
    const int HO = HIN - 2, WO = HIN - 2, WP2 = WO / 2, NP = HO * WP2;
    extern __shared__ float sm[];
    float* sx = sm;                      // 40*HIN*HIN
    float* sw = sm + 40 * HIN * HIN;     // 3600
    __shared__ float bsum[10], bsq[10];
    int b = blockIdx.x >> 2, r = blockIdx.x & 3;
    int tid = threadIdx.x;
    const float* wsl = &g_wc[layer * 14400];
    const float* inb = in + (size_t)b * 40 * HIN * HIN;
    const float* attp = g_att + (size_t)b * 4 * HIN * HIN;
    for (int idx = tid; idx < 40 * HIN * HIN; idx += NT)
        sx[idx] = inb[idx] * __ldg(&attp[idx % (4 * HIN * HIN)]);
    for (int idx = tid; idx < 3600; idx += NT) sw[idx] = wsl[r * 3600 + idx];
    if (tid < 10) { bsum[tid] = 0.f; bsq[tid] = 0.f; }
    __syncthreads();
    float ts[10], tq[10];
#pragma unroll
    for (int o = 0; o < 10; o++) { ts[o] = 0.f; tq[o] = 0.f; }
    for (int pp = tid; pp < NP; pp += NT) {
        int y = pp / WP2, x0 = (pp % WP2) * 2;
        float a0[10], a1[10];
#pragma unroll
        for (int o = 0; o < 10; o++) { a0[o] = 0.f; a1[o] = 0.f; }
        for (int is = 0; is < 40; is++) {
            const float* xb = &sx[(is * HIN + y) * HIN + x0];
            const float* wb = &sw[is * 90];
#pragma unroll
            for (int u = 0; u < 3; u++)
#pragma unroll
                for (int v = 0; v < 3; v++) {
                    float xv0 = xb[u * HIN + v];
                    float xv1 = xb[u * HIN + v + 1];
                    const float* wp = wb + (u * 3 + v) * 10;
#pragma unroll
                    for (int o = 0; o < 10; o++) {
                        a0[o] = fmaf(xv0, wp[o], a0[o]);
                        a1[o] = fmaf(xv1, wp[o], a1[o]);
                    }
                }
        }
#pragma unroll
        for (int o = 0; o < 10; o++) {
            size_t off = ((((size_t)b * 10 + o) * 4 + r) * HO + y) * WO + x0;
            out[off] = a0[o]; out[off + 1] = a1[o];
            ts[o] += a0[o] + a1[o];
            tq[o] += a0[o] * a0[o] + a1[o] * a1[o];
        }
    }
#pragma unroll
    for (int o = 0; o < 10; o++) {
        float s = warpsum(ts[o]);
        float q = warpsum(tq[o]);
        if ((tid & 31) == 0) { atomicAdd(&bsum[o], s); atomicAdd(&bsq[o], q); }
    }
    __syncthreads();
    if (tid < 10) {
        atomicAdd(&g_sum[statsIdx * 10 + tid], (double)bsum[tid]);
        atomicAdd(&g_sq[statsIdx * 10 + tid], (double)bsq[tid]);
    }
}

// ---------------- BN finalize ----------------
__global__ void bnfin(int l, const float* __restrict__ g, const float* __restrict__ bt,
                      float invN) {
    int c = threadIdx.x;
    if (c < 10) {
        double m = g_sum[l * 10 + c] * (double)invN;
        double var = g_sq[l * 10 + c] * (double)invN - m * m;
        float rstd = rsqrtf((float)var + 2e-5f);
        float sc = g[c] * rstd;
        g_scale[l * 10 + c] = sc;
        g_shift[l * 10 + c] = bt[c] - (float)m * sc;
    }
}

// ---------------- BN apply + ReLU (in place) ----------------
__global__ void bnapply(float* __restrict__ buf, int l, int hw4, int total) {
    int idx = blockIdx.x * blockDim.x + threadIdx.x;
    if (idx >= total) return;
    int c = (idx / hw4) % 10;
    float v = fmaf(buf[idx], g_scale[l * 10 + c], g_shift[l * 10 + c]);
    buf[idx] = v > 0.f ? v : 0.f;
}

// ---------------- BN apply + ReLU + 2x2 max pool (layer 2: 24x24 -> 12x12) -----
__global__ void bnpool2(const float* __restrict__ in, float* __restrict__ out, int l, int B) {
    int total = B * 10 * 4 * 144;
    int idx = blockIdx.x * blockDim.x + threadIdx.x;
    if (idx >= total) return;
    int x = idx % 12, y = (idx / 12) % 12;
    int c = (idx / 576) % 10;
    int bcs = idx / 144;
    const float* p = in + (size_t)bcs * 576 + (2 * y) * 24 + 2 * x;
    float sc = g_scale[l * 10 + c], sh = g_shift[l * 10 + c];
    float v0 = fmaf(p[0], sc, sh), v1 = fmaf(p[1], sc, sh);
    float v2 = fmaf(p[24], sc, sh), v3 = fmaf(p[25], sc, sh);
    float v = fmaxf(fmaxf(v0, v1), fmaxf(v2, v3));
    out[idx] = v > 0.f ? v : 0.f;
}

// ---------------- layer 7: GG conv 4x4 -> 1x1, then max over orientations ------
__global__ void __launch_bounds__(64) conv7k(const float* __restrict__ in,
                                             float* __restrict__ outp) {
    __shared__ float sx[640];
    __shared__ float yv[40];
    int b = blockIdx.x, tid = threadIdx.x;
    const float* attp = g_att + (size_t)b * 64;
    for (int idx = tid; idx < 640; idx += 64)
        sx[idx] = in[(size_t)b * 640 + idx] * __ldg(&attp[idx & 63]);
    __syncthreads();
    if (tid < 40) {
        int r = tid / 10, o = tid % 10;
        float acc = 0.f;
        for (int is = 0; is < 40; is++) {
#pragma unroll
            for (int t = 0; t < 16; t++)
                acc = fmaf(sx[is * 16 + t], __ldg(&g_wc7[((r * 40 + is) * 16 + t) * 10 + o]), acc);
        }
        yv[r * 10 + o] = acc;
    }
    __syncthreads();
    if (tid < 10) {
        float m = yv[tid];
        for (int r = 1; r < 4; r++) m = fmaxf(m, yv[r * 10 + tid]);
        outp[(size_t)b * 10 + tid] = m;
    }
}

// ---------------- launch ----------------
extern "C" void kernel_launch(void* const* d_in, const int* in_sizes, int n_in,
                              void* d_out, int out_size) {
    const float* x  = (const float*)d_in[0];
    const float* c1 = (const float*)d_in[1];
    const float* a1 = (const float*)d_in[2];
    const float* c2 = (const float*)d_in[3];
    const float* a2 = (const float*)d_in[4];
    const float* c3 = (const float*)d_in[5];
    const float* a3 = (const float*)d_in[6];
    const float* c4 = (const float*)d_in[7];
    const float* a4 = (const float*)d_in[8];
    const float* c5 = (const float*)d_in[9];
    const float* a5 = (const float*)d_in[10];
    const float* c6 = (const float*)d_in[11];
    const float* a6 = (const float*)d_in[12];
    const float* c7 = (const float*)d_in[13];
    const float* a7 = (const float*)d_in[14];
    const float* bn_g[6] = {(const float*)d_in[15], (const float*)d_in[17], (const float*)d_in[19],
                            (const float*)d_in[21], (const float*)d_in[23], (const float*)d_in[25]};
    const float* bn_b[6] = {(const float*)d_in[16], (const float*)d_in[18], (const float*)d_in[20],
                            (const float*)d_in[22], (const float*)d_in[24], (const float*)d_in[26]};
    float* out = (float*)d_out;

    int B = in_sizes[0] / 784;
    if (B > BMAX) B = BMAX;

    float *b0, *b1;
    cudaGetSymbolAddress((void**)&b0, g_buf0);
    cudaGetSymbolAddress((void**)&b1, g_buf1);

    const int SMEM26 = (40 * 26 * 26 + 3600) * 4;
    cudaFuncSetAttribute((const void*)convgg<26, 288>,
                         cudaFuncAttributeMaxDynamicSharedMemorySize, SMEM26);

    prepk<<<64, 128>>>(c1, c2, c3, c4, c5, c6, c7, a1, a2, a3, a4, a5, a6, a7);

    // layer 1: attention gate + lifting conv + BN/ReLU
    att1k<<<B, 256>>>(x);
    conv1k<<<B, 256>>>();
    bnfin<<<1, 32>>>(0, bn_g[0], bn_b[0], 1.f / (float)(B * 4 * 676));
    {
        int tot = B * 40 * 676;
        bnapply<<<(tot + 255) / 256, 256>>>(b0, 0, 4 * 676, tot);
    }

    // layer 2: 26 -> 24, then 2x2 pool -> 12
    {
        int tp = B * 4 * 676;
        poolk<26><<<(tp + 255) / 256, 256>>>(b0, B);
        attk<26><<<B * 4, 256>>>(0);
        convgg<26, 288><<<B * 4, 288, SMEM26>>>(b0, b1, 0, 1);
        bnfin<<<1, 32>>>(1, bn_g[1], bn_b[1], 1.f / (float)(B * 4 * 576));
        int tot = B * 10 * 4 * 144;
        bnpool2<<<(tot + 255) / 256, 256>>>(b1, b0, 1, B);
    }

    // layer 3: 12 -> 10
    {
        int tp = B * 4 * 144;
        poolk<12><<<(tp + 255) / 256, 256>>>(b0, B);
        attk<12><<<B * 4, 256>>>(1);
        convgg<12, 128><<<B * 4, 128, (40 * 144 + 3600) * 4>>>(b0, b1, 1, 2);
        bnfin<<<1, 32>>>(2, bn_g[2], bn_b[2], 1.f / (float)(B * 4 * 100));
        int tot = B * 40 * 100;
        bnapply<<<(tot + 255) / 256, 256>>>(b1, 2, 4 * 100, tot);
    }

    // layer 4: 10 -> 8
    {
        int tp = B * 4 * 100;
        poolk<10><<<(tp + 255) / 256, 256>>>(b1, B);
        attk<10><<<B * 4, 256>>>(2);
        convgg<10, 64><<<B * 4, 64, (40 * 100 + 3600) * 4>>>(b1, b0, 2, 3);
        bnfin<<<1, 32>>>(3, bn_g[3], bn_b[3], 1.f / (float)(B * 4 * 64));
        int tot = B * 40 * 64;
        bnapply<<<(tot + 255) / 256, 256>>>(b0, 3, 4 * 64, tot);
    }

    // layer 5: 8 -> 6
    {
        int tp = B * 4 * 64;
        poolk<8><<<(tp + 255) / 256, 256>>>(b0, B);
        attk<8><<<B * 4, 256>>>(3);
        convgg<8, 64><<<B * 4, 64, (40 * 64 + 3600) * 4>>>(b0, b1, 3, 4);
        bnfin<<<1, 32>>>(4, bn_g[4], bn_b[4], 1.f / (float)(B * 4 * 36));
        int tot = B * 40 * 36;
        bnapply<<<(tot + 255) / 256, 256>>>(b1, 4, 4 * 36, tot);
    }

    // layer 6: 6 -> 4
    {
        int tp = B * 4 * 36;
        poolk<6><<<(tp + 255) / 256, 256>>>(b1, B);
        attk<6><<<B * 4, 256>>>(4);
        convgg<6, 64><<<B * 4, 64, (40 * 36 + 3600) * 4>>>(b1, b0, 4, 5);
        bnfin<<<1, 32>>>(5, bn_g[5], bn_b[5], 1.f / (float)(B * 4 * 16));
        int tot = B * 40 * 16;
        bnapply<<<(tot + 255) / 256, 256>>>(b0, 5, 4 * 16, tot);
    }

    // layer 7: 4x4 -> 1x1, max over orientations
    {
        int tp = B * 4 * 16;
        poolk<4><<<(tp + 255) / 256, 256>>>(b0, B);
        attk<4><<<B * 4, 256>>>(5);
        conv7k<<<B, 64>>>(b0, out);
    }
}

// round 4
// speedup vs baseline: 1.8887x; 1.8887x over previous
#include <cuda_runtime.h>
#include <cstdint>
#include <math.h>

// ---------------- static device scratch ----------------
#define BMAX 2048
__device__ float g_buf0[BMAX * 10 * 4 * 26 * 26];   // ~221 MB
__device__ float g_buf1[BMAX * 10 * 4 * 24 * 24];   // ~189 MB
__device__ float g_att [BMAX * 4 * 26 * 26];        // att maps / gated L1 input
__device__ float g_pool[BMAX * 2 * 4 * 26 * 26];    // pooled (mean,max) for attention

__device__ double g_sum[60], g_sq[60];
__device__ float  g_scale[60], g_shift[60];

// rotated weights
__device__ float g_wl[4 * 3 * 3 * 10];                           // lifting [r][u][v][o]
__device__ __align__(16) float g_wc[5 * 4 * 10 * 4 * 3 * 3 * 10]; // GG convs 2..6 [l][r][i][s][u][v][o]
__device__ float g_wc7[4 * 10 * 4 * 4 * 4 * 10];                 // GG conv 7 [r][i][s][u][v][o]
__device__ float g_wa1[49];                                      // L1 att (mean+max summed)
__device__ float g_wa[6 * 4 * 2 * 4 * 7 * 7];                    // GG att 2..7 [l][r][i][s][u][v]

typedef unsigned long long u64;

__device__ __forceinline__ u64 pk2(float lo, float hi) {
    u64 r; asm("mov.b64 %0,{%1,%2};" : "=l"(r) : "f"(lo), "f"(hi)); return r;
}
__device__ __forceinline__ void upk2(u64 v, float& lo, float& hi) {
    asm("mov.b64 {%0,%1},%2;" : "=f"(lo), "=f"(hi) : "l"(v));
}
__device__ __forceinline__ u64 ffma2(u64 a, u64 b, u64 c) {
    u64 d; asm("fma.rn.f32x2 %0,%1,%2,%3;" : "=l"(d) : "l"(a), "l"(b), "l"(c)); return d;
}

__device__ __forceinline__ void rotmap(int r, int u, int v, int K, int& su, int& sv) {
    switch (r & 3) {
        case 0: su = u;         sv = v;         break;
        case 1: su = v;         sv = K - 1 - u; break;
        case 2: su = K - 1 - u; sv = K - 1 - v; break;
        default: su = K - 1 - v; sv = u;        break;
    }
}

__device__ __forceinline__ float warpsum(float v) {
    for (int o = 16; o > 0; o >>= 1) v += __shfl_down_sync(0xffffffffu, v, o);
    return v;
}

// ---------------- prep: rotate weights, zero stats ----------------
__global__ void prepk(const float* c1, const float* c2, const float* c3, const float* c4,
                      const float* c5, const float* c6, const float* c7,
                      const float* a1, const float* a2, const float* a3, const float* a4,
                      const float* a5, const float* a6, const float* a7) {
    int tid = blockIdx.x * blockDim.x + threadIdx.x;
    int nth = gridDim.x * blockDim.x;
    const float* cws[5] = {c2, c3, c4, c5, c6};
    const float* aws[6] = {a2, a3, a4, a5, a6, a7};

    for (int idx = tid; idx < 360; idx += nth) {
        int o = idx % 10, t = idx / 10;
        int v = t % 3; t /= 3; int u = t % 3; int r = t / 3;
        int su, sv; rotmap(r, u, v, 3, su, sv);
        g_wl[idx] = c1[o * 9 + su * 3 + sv];
    }
    for (int idx = tid; idx < 5 * 14400; idx += nth) {
        int o = idx % 10; int t = idx / 10;
        int v = t % 3; t /= 3; int u = t % 3; t /= 3;
        int s = t & 3; t >>= 2; int i = t % 10; t /= 10;
        int r = t & 3; int l = t >> 2;
        int sp = (s - r) & 3; int su, sv; rotmap(r, u, v, 3, su, sv);
        g_wc[idx] = cws[l][((o * 10 + i) * 4 + sp) * 9 + su * 3 + sv];
    }
    for (int idx = tid; idx < 25600; idx += nth) {
        int o = idx % 10; int t = idx / 10;
        int v = t & 3; t >>= 2; int u = t & 3; t >>= 2;
        int s = t & 3; t >>= 2; int i = t % 10; int r = t / 10;
        int sp = (s - r) & 3; int su, sv; rotmap(r, u, v, 4, su, sv);
        g_wc7[idx] = c7[((o * 10 + i) * 4 + sp) * 16 + su * 4 + sv];
    }
    for (int idx = tid; idx < 49; idx += nth) g_wa1[idx] = a1[idx] + a1[49 + idx];
    for (int idx = tid; idx < 6 * 1568; idx += nth) {
        int v = idx % 7; int t = idx / 7;
        int u = t % 7; t /= 7; int s = t & 3; t >>= 2;
        int i = t & 1; t >>= 1; int r = t & 3; int l = t >> 2;
        int sp = (s - r) & 3; int su, sv; rotmap(r, u, v, 7, su, sv);
        g_wa[idx] = aws[l][(i * 4 + sp) * 49 + su * 7 + sv];
    }
    for (int idx = tid; idx < 60; idx += nth) { g_sum[idx] = 0.0; g_sq[idx] = 0.0; }
}

// ---------------- layer 1 attention + gating ----------------
__global__ void __launch_bounds__(256) att1k(const float* __restrict__ x) {
    __shared__ float xt[34 * 34];
    __shared__ float w[49];
    int b = blockIdx.x, tid = threadIdx.x;
    for (int i = tid; i < 34 * 34; i += 256) xt[i] = 0.f;
    for (int i = tid; i < 49; i += 256) w[i] = g_wa1[i];
    __syncthreads();
    for (int i = tid; i < 784; i += 256) {
        int y = i / 28, xx = i % 28;
        xt[(y + 3) * 34 + xx + 3] = x[(size_t)b * 784 + i];
    }
    __syncthreads();
    for (int p = tid; p < 784; p += 256) {
        int y = p / 28, xx = p % 28;
        float acc = 0.f;
#pragma unroll
        for (int u = 0; u < 7; u++)
#pragma unroll
            for (int v = 0; v < 7; v++)
                acc = fmaf(xt[(y + u) * 34 + xx + v], w[u * 7 + v], acc);
        float xv = xt[(y + 3) * 34 + xx + 3];
        g_att[(size_t)b * 784 + p] = xv * (1.f / (1.f + expf(-acc)));
    }
}

// ---------------- layer 1 lifting conv (valid 3x3, 4 rotations) ----------------
__global__ void __launch_bounds__(256) conv1k() {
    __shared__ float sx[784];
    __shared__ float sw[360];
    __shared__ float bsum[10], bsq[10];
    int b = blockIdx.x, tid = threadIdx.x;
    for (int i = tid; i < 784; i += 256) sx[i] = g_att[(size_t)b * 784 + i];
    for (int i = tid; i < 360; i += 256) sw[i] = g_wl[i];
    if (tid < 10) { bsum[tid] = 0.f; bsq[tid] = 0.f; }
    __syncthreads();
    float ts[10], tq[10];
#pragma unroll
    for (int o = 0; o < 10; o++) { ts[o] = 0.f; tq[o] = 0.f; }
    for (int r = 0; r < 4; r++) {
        for (int pp = tid; pp < 338; pp += 256) {
            int y = pp / 13, x0 = (pp % 13) * 2;
            float a0[10], a1[10];
#pragma unroll
            for (int o = 0; o < 10; o++) { a0[o] = 0.f; a1[o] = 0.f; }
#pragma unroll
            for (int u = 0; u < 3; u++)
#pragma unroll
                for (int v = 0; v < 3; v++) {
                    float xv0 = sx[(y + u) * 28 + x0 + v];
                    float xv1 = sx[(y + u) * 28 + x0 + v + 1];
                    const float* wp = &sw[((r * 3 + u) * 3 + v) * 10];
#pragma unroll
                    for (int o = 0; o < 10; o++) {
                        a0[o] = fmaf(xv0, wp[o], a0[o]);
                        a1[o] = fmaf(xv1, wp[o], a1[o]);
                    }
                }
#pragma unroll
            for (int o = 0; o < 10; o++) {
                size_t off = ((((size_t)b * 10 + o) * 4 + r) * 26 + y) * 26 + x0;
                g_buf0[off] = a0[o]; g_buf0[off + 1] = a1[o];
                ts[o] += a0[o] + a1[o];
                tq[o] += a0[o] * a0[o] + a1[o] * a1[o];
            }
        }
    }
#pragma unroll
    for (int o = 0; o < 10; o++) {
        float s = warpsum(ts[o]);
        float q = warpsum(tq[o]);
        if ((tid & 31) == 0) { atomicAdd(&bsum[o], s); atomicAdd(&bsq[o], q); }
    }
    __syncthreads();
    if (tid < 10) {
        atomicAdd(&g_sum[tid], (double)bsum[tid]);
        atomicAdd(&g_sq[tid], (double)bsq[tid]);
    }
}

// ---------------- pooled (mean,max over channels), optional fused BN+ReLU -------
template <int HIN>
__global__ void poolk(const float* __restrict__ in, int B, int bnIdx) {
    const int H2 = HIN * HIN;
    int total = B * 4 * H2;
    for (int idx = blockIdx.x * blockDim.x + threadIdx.x; idx < total;
         idx += gridDim.x * blockDim.x) {
        int pos = idx % H2;
        int s = (idx / H2) & 3;
        int b = idx / (4 * H2);
        const float* p = in + ((size_t)b * 40 + s) * H2 + pos;
        float sum = 0.f, mx = -3.4e38f;
#pragma unroll
        for (int c = 0; c < 10; c++) {
            float v = p[(size_t)c * 4 * H2];
            if (bnIdx >= 0) {
                v = fmaf(v, __ldg(&g_scale[bnIdx * 10 + c]), __ldg(&g_shift[bnIdx * 10 + c]));
                v = v > 0.f ? v : 0.f;
            }
            sum += v; mx = fmaxf(mx, v);
        }
        g_pool[((size_t)b * 8 + s) * H2 + pos]     = sum / 10.0f;
        g_pool[((size_t)b * 8 + 4 + s) * H2 + pos] = mx;
    }
}

// ---------------- GG attention conv (7x7 SAME) + sigmoid, 4px register blocked --
template <int H, int NT>
__global__ void __launch_bounds__(NT) attk(int layer) {
    constexpr int H2 = H * H, PW = H + 6, PW4 = (PW + 3) & ~3;
    constexpr int NQ = (H + 3) / 4, TASKS = H * NQ;
    __shared__ __align__(16) float pt[8 * PW4 * PW4 + 16];
    __shared__ float wa[392];
    int b = blockIdx.x >> 2, r = blockIdx.x & 3;
    int tid = threadIdx.x;
    for (int i = tid; i < 8 * PW4 * PW4 + 16; i += NT) pt[i] = 0.f;
    for (int i = tid; i < 392; i += NT) wa[i] = g_wa[layer * 1568 + r * 392 + i];
    __syncthreads();
    const float* pb = g_pool + (size_t)b * 8 * H2;
    for (int idx = tid; idx < 8 * H2; idx += NT) {
        int js = idx / H2, pos = idx - js * H2;
        int y = pos / H, x = pos - y * H;
        pt[(js * PW4 + y + 3) * PW4 + x + 3] = pb[idx];
    }
    __syncthreads();
    for (int task = tid; task < TASKS; task += NT) {
        int q = task % NQ, y = task / NQ;
        int x0 = q * 4;
        float a0 = 0.f, a1 = 0.f, a2 = 0.f, a3 = 0.f;
#pragma unroll
        for (int js = 0; js < 8; js++) {
#pragma unroll
            for (int u = 0; u < 7; u++) {
                const float* rowp = &pt[(js * PW4 + y + u) * PW4 + x0];
                float4 A = *(const float4*)rowp;
                float4 Bv = *(const float4*)(rowp + 4);
                float2 Cv = *(const float2*)(rowp + 8);
                float rr[10] = {A.x, A.y, A.z, A.w, Bv.x, Bv.y, Bv.z, Bv.w, Cv.x, Cv.y};
                const float* wb = &wa[js * 49 + u * 7];
#pragma unroll
                for (int v = 0; v < 7; v++) {
                    float w = wb[v];
                    a0 = fmaf(rr[v], w, a0);
                    a1 = fmaf(rr[v + 1], w, a1);
                    a2 = fmaf(rr[v + 2], w, a2);
                    a3 = fmaf(rr[v + 3], w, a3);
                }
            }
        }
        float* ob = &g_att[((size_t)b * 4 + r) * H2 + y * H];
        if (x0 + 0 < H) ob[x0 + 0] = 1.f / (1.f + expf(-a0));
        if (x0 + 1 < H) ob[x0 + 1] = 1.f / (1.f + expf(-a1));
        if (x0 + 2 < H) ob[x0 + 2] = 1.f / (1.f + expf(-a2));
        if (x0 + 3 < H) ob[x0 + 3] = 1.f / (1.f + expf(-a3));
    }
}

// ---------------- main GG conv: all 4 rotations in one block, f32x2 math --------
// Accumulator lanes pack output-channel pairs (2k, 2k+1); weights load as LDS.64.
// Input loaded once per image, gated by attention (+ optional BN+ReLU of producer).
template <int H, int NT, int PXCH>
__global__ void __launch_bounds__(NT) convgg(const float* __restrict__ in,
                                             float* __restrict__ out,
                                             int layer, int statsIdx, int bnIdx) {
    constexpr int HO = H - 2, WO = H - 2;
    constexpr int HP = (H + 3) & ~3;
    constexpr int NQ = (WO + PXCH - 1) / PXCH;
    constexpr int TASKS = 4 * HO * NQ;
    constexpr int H2 = H * H;
    extern __shared__ float sm[];
    float* sx = sm;                          // 40*H*HP (+16 pad)
    float* sw = sm + 40 * H * HP + 16;       // 14400 = 4 rotations x 3600
    __shared__ float bsum[10], bsq[10];
    int b = blockIdx.x;
    int tid = threadIdx.x;
    const float* inb = in + (size_t)b * 40 * H2;
    const float* attp = g_att + (size_t)b * 4 * H2;

    if (tid < 16) sx[40 * H * HP + tid] = 0.f;
    for (int idx = tid; idx < 40 * H2; idx += NT) {
        int is = idx / H2;
        int pos = idx - is * H2;
        int y = pos / H, x = pos - y * H;
        float v = inb[idx];
        if (bnIdx >= 0) {
            int c = is >> 2;
            v = fmaf(v, __ldg(&g_scale[bnIdx * 10 + c]), __ldg(&g_shift[bnIdx * 10 + c]));
            v = v > 0.f ? v : 0.f;
        }
        v *= __ldg(&attp[(is & 3) * H2 + pos]);
        sx[(is * H + y) * HP + x] = v;
    }
    {
        const float4* wg = (const float4*)&g_wc[layer * 14400];
        float4* swv = (float4*)sw;
        for (int idx = tid; idx < 3600; idx += NT) swv[idx] = wg[idx];
    }
    if (tid < 10) { bsum[tid] = 0.f; bsq[tid] = 0.f; }
    __syncthreads();

    float ts[10], tq[10];
#pragma unroll
    for (int o = 0; o < 10; o++) { ts[o] = 0.f; tq[o] = 0.f; }

    for (int task = tid; task < TASKS; task += NT) {
        int q = task % NQ;
        int y = (task / NQ) % HO;
        int r = task / (NQ * HO);
        int x0 = q * PXCH;
        u64 acc[PXCH][5];
#pragma unroll
        for (int p = 0; p < PXCH; p++)
#pragma unroll
            for (int k = 0; k < 5; k++) acc[p][k] = 0ull;

        const float* wr = &sw[r * 3600];
        const float* xb0 = &sx[y * HP + x0];
        for (int is = 0; is < 40; is++) {
            const float* xb = xb0 + is * H * HP;
            const float* wb = wr + is * 90;
#pragma unroll
            for (int u = 0; u < 3; u++) {
                u64 xd[PXCH + 2];
                if (PXCH == 4) {
                    // x0 multiple of 4, HP multiple of 4 -> 16B aligned
                    float4 v4 = *(const float4*)(xb + u * HP);
                    float2 v2 = *(const float2*)(xb + u * HP + 4);
                    xd[0] = pk2(v4.x, v4.x); xd[1] = pk2(v4.y, v4.y);
                    xd[2] = pk2(v4.z, v4.z); xd[3] = pk2(v4.w, v4.w);
                    xd[4] = pk2(v2.x, v2.x); xd[5] = pk2(v2.y, v2.y);
                } else {
                    // x0 even -> 8B aligned; use two float2 loads
                    float2 vA = *(const float2*)(xb + u * HP);
                    float2 vB = *(const float2*)(xb + u * HP + 2);
                    xd[0] = pk2(vA.x, vA.x); xd[1] = pk2(vA.y, vA.y);
                    xd[2] = pk2(vB.x, vB.x); xd[3] = pk2(vB.y, vB.y);
                }
#pragma unroll
                for (int v = 0; v < 3; v++) {
                    const u64* wp = (const u64*)(wb + u * 30 + v * 10);
#pragma unroll
                    for (int k = 0; k < 5; k++) {
                        u64 w2 = wp[k];
#pragma unroll
                        for (int p = 0; p < PXCH; p++)
                            acc[p][k] = ffma2(xd[v + p], w2, acc[p][k]);
                    }
                }
            }
        }
#pragma unroll
        for (int p = 0; p < PXCH; p++) {
            int x = x0 + p;
            if (x < WO) {
#pragma unroll
                for (int k = 0; k < 5; k++) {
                    float lo, hi; upk2(acc[p][k], lo, hi);
                    ts[2 * k] += lo;     tq[2 * k] += lo * lo;
                    ts[2 * k + 1] += hi; tq[2 * k + 1] += hi * hi;
                    size_t o0 = ((((size_t)b * 10 + 2 * k) * 4 + r) * HO + y) * WO + x;
                    out[o0] = lo;
                    out[o0 + (size_t)4 * HO * WO] = hi;
                }
            }
        }
    }
#pragma unroll
    for (int o = 0; o < 10; o++) {
        float s = warpsum(ts[o]);
        float qv = warpsum(tq[o]);
        if ((tid & 31) == 0) { atomicAdd(&bsum[o], s); atomicAdd(&bsq[o], qv); }
    }
    __syncthreads();
    if (tid < 10) {
        atomicAdd(&g_sum[statsIdx * 10 + tid], (double)bsum[tid]);
        atomicAdd(&g_sq[statsIdx * 10 + tid], (double)bsq[tid]);
    }
}

// ---------------- BN finalize ----------------
__global__ void bnfin(int l, const float* __restrict__ g, const float* __restrict__ bt,
                      float invN) {
    int c = threadIdx.x;
    if (c < 10) {
        double m = g_sum[l * 10 + c] * (double)invN;
        double var = g_sq[l * 10 + c] * (double)invN - m * m;
        float rstd = rsqrtf((float)var + 2e-5f);
        float sc = g[c] * rstd;
        g_scale[l * 10 + c] = sc;
        g_shift[l * 10 + c] = bt[c] - (float)m * sc;
    }
}

// ---------------- BN apply + ReLU + 2x2 max pool (layer 2: 24x24 -> 12x12) -----
__global__ void bnpool2(const float* __restrict__ in, float* __restrict__ out, int l, int B) {
    int total = B * 10 * 4 * 144;
    int idx = blockIdx.x * blockDim.x + threadIdx.x;
    if (idx >= total) return;
    int x = idx % 12, y = (idx / 12) % 12;
    int c = (idx / 576) % 10;
    int bcs = idx / 144;
    const float* p = in + (size_t)bcs * 576 + (2 * y) * 24 + 2 * x;
    float sc = g_scale[l * 10 + c], sh = g_shift[l * 10 + c];
    float v0 = fmaf(p[0], sc, sh), v1 = fmaf(p[1], sc, sh);
    float v2 = fmaf(p[24], sc, sh), v3 = fmaf(p[25], sc, sh);
    float v = fmaxf(fmaxf(v0, v1), fmaxf(v2, v3));
    out[idx] = v > 0.f ? v : 0.f;
}

// ---------------- layer 7: BN5+ReLU+gate, GG conv 4x4 -> 1x1, orientation max --
__global__ void __launch_bounds__(64) conv7k(const float* __restrict__ in,
                                             float* __restrict__ outp) {
    __shared__ float sx[640];
    __shared__ float yv[40];
    int b = blockIdx.x, tid = threadIdx.x;
    const float* attp = g_att + (size_t)b * 64;
    for (int idx = tid; idx < 640; idx += 64) {
        int c = idx >> 6;
        float v = in[(size_t)b * 640 + idx];
        v = fmaf(v, __ldg(&g_scale[50 + c]), __ldg(&g_shift[50 + c]));
        v = v > 0.f ? v : 0.f;
        sx[idx] = v * __ldg(&attp[idx & 63]);
    }
    __syncthreads();
    if (tid < 40) {
        int r = tid / 10, o = tid % 10;
        float acc = 0.f;
        for (int is = 0; is < 40; is++) {
#pragma unroll
            for (int t = 0; t < 16; t++)
                acc = fmaf(sx[is * 16 + t], __ldg(&g_wc7[((r * 40 + is) * 16 + t) * 10 + o]), acc);
        }
        yv[r * 10 + o] = acc;
    }
    __syncthreads();
    if (tid < 10) {
        float m = yv[tid];
        for (int r = 1; r < 4; r++) m = fmaxf(m, yv[r * 10 + tid]);
        outp[(size_t)b * 10 + tid] = m;
    }
}

// ---------------- launch ----------------
extern "C" void kernel_launch(void* const* d_in, const int* in_sizes, int n_in,
                              void* d_out, int out_size) {
    const float* x  = (const float*)d_in[0];
    const float* c1 = (const float*)d_in[1];
    const float* a1 = (const float*)d_in[2];
    const float* c2 = (const float*)d_in[3];
    const float* a2 = (const float*)d_in[4];
    const float* c3 = (const float*)d_in[5];
    const float* a3 = (const float*)d_in[6];
    const float* c4 = (const float*)d_in[7];
    const float* a4 = (const float*)d_in[8];
    const float* c5 = (const float*)d_in[9];
    const float* a5 = (const float*)d_in[10];
    const float* c6 = (const float*)d_in[11];
    const float* a6 = (const float*)d_in[12];
    const float* c7 = (const float*)d_in[13];
    const float* a7 = (const float*)d_in[14];
    const float* bn_g[6] = {(const float*)d_in[15], (const float*)d_in[17], (const float*)d_in[19],
                            (const float*)d_in[21], (const float*)d_in[23], (const float*)d_in[25]};
    const float* bn_b[6] = {(const float*)d_in[16], (const float*)d_in[18], (const float*)d_in[20],
                            (const float*)d_in[22], (const float*)d_in[24], (const float*)d_in[26]};
    float* out = (float*)d_out;

    int B = in_sizes[0] / 784;
    if (B > BMAX) B = BMAX;

    float *b0, *b1;
    cudaGetSymbolAddress((void**)&b0, g_buf0);
    cudaGetSymbolAddress((void**)&b1, g_buf1);

    const int SM26 = (40 * 26 * 28 + 16 + 14400) * 4;
    const int SM12 = (40 * 12 * 12 + 16 + 14400) * 4;
    const int SM10 = (40 * 10 * 12 + 16 + 14400) * 4;
    const int SM8  = (40 * 8 * 8 + 16 + 14400) * 4;
    const int SM6  = (40 * 6 * 8 + 16 + 14400) * 4;
    cudaFuncSetAttribute((const void*)convgg<26, 288, 4>, cudaFuncAttributeMaxDynamicSharedMemorySize, SM26);
    cudaFuncSetAttribute((const void*)convgg<12, 128, 4>, cudaFuncAttributeMaxDynamicSharedMemorySize, SM12);
    cudaFuncSetAttribute((const void*)convgg<10, 128, 2>, cudaFuncAttributeMaxDynamicSharedMemorySize, SM10);
    cudaFuncSetAttribute((const void*)convgg<8, 96, 2>,   cudaFuncAttributeMaxDynamicSharedMemorySize, SM8);
    cudaFuncSetAttribute((const void*)convgg<6, 64, 2>,   cudaFuncAttributeMaxDynamicSharedMemorySize, SM6);

    prepk<<<64, 128>>>(c1, c2, c3, c4, c5, c6, c7, a1, a2, a3, a4, a5, a6, a7);

    // layer 1: attention gate + lifting conv (raw out + stats0)
    att1k<<<B, 256>>>(x);
    conv1k<<<B, 256>>>();
    bnfin<<<1, 32>>>(0, bn_g[0], bn_b[0], 1.f / (float)(B * 4 * 676));

    // layer 2: 26 -> 24 (BN0 fused into consumers), then BN1+pool -> 12
    {
        int tp = B * 4 * 676;
        poolk<26><<<(tp + 255) / 256, 256>>>(b0, B, 0);
        attk<26, 192><<<B * 4, 192>>>(0);
        convgg<26, 288, 4><<<B, 288, SM26>>>(b0, b1, 0, 1, 0);
        bnfin<<<1, 32>>>(1, bn_g[1], bn_b[1], 1.f / (float)(B * 4 * 576));
        int tot = B * 10 * 4 * 144;
        bnpool2<<<(tot + 255) / 256, 256>>>(b1, b0, 1, B);
    }

    // layer 3: 12 -> 10 (input already final)
    {
        int tp = B * 4 * 144;
        poolk<12><<<(tp + 255) / 256, 256>>>(b0, B, -1);
        attk<12, 64><<<B * 4, 64>>>(1);
        convgg<12, 128, 4><<<B, 128, SM12>>>(b0, b1, 1, 2, -1);
        bnfin<<<1, 32>>>(2, bn_g[2], bn_b[2], 1.f / (float)(B * 4 * 100));
    }

    // layer 4: 10 -> 8 (BN2 fused)
    {
        int tp = B * 4 * 100;
        poolk<10><<<(tp + 255) / 256, 256>>>(b1, B, 2);
        attk<10, 32><<<B * 4, 32>>>(2);
        convgg<10, 128, 2><<<B, 128, SM10>>>(b1, b0, 2, 3, 2);
        bnfin<<<1, 32>>>(3, bn_g[3], bn_b[3], 1.f / (float)(B * 4 * 64));
    }

    // layer 5: 8 -> 6 (BN3 fused)
    {
        int tp = B * 4 * 64;
        poolk<8><<<(tp + 255) / 256, 256>>>(b0, B, 3);
        attk<8, 32><<<B * 4, 32>>>(3);
        convgg<8, 96, 2><<<B, 96, SM8>>>(b0, b1, 3, 4, 3);
        bnfin<<<1, 32>>>(4, bn_g[4], bn_b[4], 1.f / (float)(B * 4 * 36));
    }

    // layer 6: 6 -> 4 (BN4 fused)
    {
        int tp = B * 4 * 36;
        poolk<6><<<(tp + 255) / 256, 256>>>(b1, B, 4);
        attk<6, 32><<<B * 4, 32>>>(4);
        convgg<6, 64, 2><<<B, 64, SM6>>>(b1, b0, 4, 5, 4);
        bnfin<<<1, 32>>>(5, bn_g[5], bn_b[5], 1.f / (float)(B * 4 * 16));
    }

    // layer 7: BN5 fused, 4x4 -> 1x1, max over orientations
    {
        int tp = B * 4 * 16;
        poolk<4><<<(tp + 255) / 256, 256>>>(b0, B, 5);
        attk<4, 32><<<B * 4, 32>>>(5);
        conv7k<<<B, 64>>>(b0, out);
    }
}

// round 5
// speedup vs baseline: 1.9328x; 1.0233x over previous
#include <cuda_runtime.h>
#include <cstdint>
#include <math.h>

#define BMAX 2048
__device__ float g_buf0[BMAX * 10 * 4 * 26 * 26];
__device__ float g_buf1[BMAX * 10 * 4 * 24 * 24];
__device__ float g_att [BMAX * 4 * 26 * 26];
__device__ float g_pool[BMAX * 2 * 4 * 26 * 26];

__device__ double g_sum[60], g_sq[60];

__device__ float g_wl[4 * 3 * 3 * 10];
__device__ __align__(16) float g_wc[5 * 4 * 10 * 4 * 3 * 3 * 10];
__device__ float g_wc7[4 * 10 * 4 * 4 * 4 * 10];
__device__ float g_wa1[49];
__device__ float g_wa[6 * 4 * 2 * 4 * 7 * 7];

typedef unsigned long long u64;

__device__ __forceinline__ u64 pk2(float lo, float hi) {
    u64 r; asm("mov.b64 %0,{%1,%2};" : "=l"(r) : "f"(lo), "f"(hi)); return r;
}
__device__ __forceinline__ void upk2(u64 v, float& lo, float& hi) {
    asm("mov.b64 {%0,%1},%2;" : "=f"(lo), "=f"(hi) : "l"(v));
}
__device__ __forceinline__ u64 ffma2(u64 a, u64 b, u64 c) {
    u64 d; asm("fma.rn.f32x2 %0,%1,%2,%3;" : "=l"(d) : "l"(a), "l"(b), "l"(c)); return d;
}

__device__ __forceinline__ void rotmap(int r, int u, int v, int K, int& su, int& sv) {
    switch (r & 3) {
        case 0: su = u;         sv = v;         break;
        case 1: su = v;         sv = K - 1 - u; break;
        case 2: su = K - 1 - u; sv = K - 1 - v; break;
        default: su = K - 1 - v; sv = u;        break;
    }
}

__device__ __forceinline__ float warpsum(float v) {
    for (int o = 16; o > 0; o >>= 1) v += __shfl_down_sync(0xffffffffu, v, o);
    return v;
}

// compute BN scale/shift into smem (threads 0..9); pass bnIdx<0 for identity
__device__ __forceinline__ void bn_smem(int tid, int bnIdx, const float* bng,
                                        const float* bnb, float invN,
                                        float* sc, float* sh) {
    if (tid < 10) {
        if (bnIdx >= 0) {
            double m = g_sum[bnIdx * 10 + tid] * (double)invN;
            double var = g_sq[bnIdx * 10 + tid] * (double)invN - m * m;
            float rstd = rsqrtf((float)var + 2e-5f);
            float s = bng[tid] * rstd;
            sc[tid] = s; sh[tid] = bnb[tid] - (float)m * s;
        } else { sc[tid] = 1.f; sh[tid] = 0.f; }
    }
}

// ---------------- prep ----------------
__global__ void prepk(const float* c1, const float* c2, const float* c3, const float* c4,
                      const float* c5, const float* c6, const float* c7,
                      const float* a1, const float* a2, const float* a3, const float* a4,
                      const float* a5, const float* a6, const float* a7) {
    int tid = blockIdx.x * blockDim.x + threadIdx.x;
    int nth = gridDim.x * blockDim.x;
    const float* cws[5] = {c2, c3, c4, c5, c6};
    const float* aws[6] = {a2, a3, a4, a5, a6, a7};

    for (int idx = tid; idx < 360; idx += nth) {
        int o = idx % 10, t = idx / 10;
        int v = t % 3; t /= 3; int u = t % 3; int r = t / 3;
        int su, sv; rotmap(r, u, v, 3, su, sv);
        g_wl[idx] = c1[o * 9 + su * 3 + sv];
    }
    for (int idx = tid; idx < 5 * 14400; idx += nth) {
        int o = idx % 10; int t = idx / 10;
        int v = t % 3; t /= 3; int u = t % 3; t /= 3;
        int s = t & 3; t >>= 2; int i = t % 10; t /= 10;
        int r = t & 3; int l = t >> 2;
        int sp = (s - r) & 3; int su, sv; rotmap(r, u, v, 3, su, sv);
        g_wc[idx] = cws[l][((o * 10 + i) * 4 + sp) * 9 + su * 3 + sv];
    }
    for (int idx = tid; idx < 25600; idx += nth) {
        int o = idx % 10; int t = idx / 10;
        int v = t & 3; t >>= 2; int u = t & 3; t >>= 2;
        int s = t & 3; t >>= 2; int i = t % 10; int r = t / 10;
        int sp = (s - r) & 3; int su, sv; rotmap(r, u, v, 4, su, sv);
        g_wc7[idx] = c7[((o * 10 + i) * 4 + sp) * 16 + su * 4 + sv];
    }
    for (int idx = tid; idx < 49; idx += nth) g_wa1[idx] = a1[idx] + a1[49 + idx];
    for (int idx = tid; idx < 6 * 1568; idx += nth) {
        int v = idx % 7; int t = idx / 7;
        int u = t % 7; t /= 7; int s = t & 3; t >>= 2;
        int i = t & 1; t >>= 1; int r = t & 3; int l = t >> 2;
        int sp = (s - r) & 3; int su, sv; rotmap(r, u, v, 7, su, sv);
        g_wa[idx] = aws[l][(i * 4 + sp) * 49 + su * 7 + sv];
    }
    for (int idx = tid; idx < 60; idx += nth) { g_sum[idx] = 0.0; g_sq[idx] = 0.0; }
}

// ---------------- layer 1 attention + gating ----------------
__global__ void __launch_bounds__(256) att1k(const float* __restrict__ x) {
    __shared__ float xt[34 * 34];
    __shared__ float w[49];
    int b = blockIdx.x, tid = threadIdx.x;
    for (int i = tid; i < 34 * 34; i += 256) xt[i] = 0.f;
    for (int i = tid; i < 49; i += 256) w[i] = g_wa1[i];
    __syncthreads();
    for (int i = tid; i < 784; i += 256) {
        int y = i / 28, xx = i % 28;
        xt[(y + 3) * 34 + xx + 3] = x[(size_t)b * 784 + i];
    }
    __syncthreads();
    for (int p = tid; p < 784; p += 256) {
        int y = p / 28, xx = p % 28;
        float acc = 0.f;
#pragma unroll
        for (int u = 0; u < 7; u++)
#pragma unroll
            for (int v = 0; v < 7; v++)
                acc = fmaf(xt[(y + u) * 34 + xx + v], w[u * 7 + v], acc);
        float xv = xt[(y + 3) * 34 + xx + 3];
        g_att[(size_t)b * 784 + p] = xv * (1.f / (1.f + expf(-acc)));
    }
}

// ---------------- layer 1 lifting conv ----------------
__global__ void __launch_bounds__(256) conv1k() {
    __shared__ float sx[784];
    __shared__ float sw[360];
    __shared__ float bsum[10], bsq[10];
    int b = blockIdx.x, tid = threadIdx.x;
    for (int i = tid; i < 784; i += 256) sx[i] = g_att[(size_t)b * 784 + i];
    for (int i = tid; i < 360; i += 256) sw[i] = g_wl[i];
    if (tid < 10) { bsum[tid] = 0.f; bsq[tid] = 0.f; }
    __syncthreads();
    float ts[10], tq[10];
#pragma unroll
    for (int o = 0; o < 10; o++) { ts[o] = 0.f; tq[o] = 0.f; }
    for (int r = 0; r < 4; r++) {
        for (int pp = tid; pp < 338; pp += 256) {
            int y = pp / 13, x0 = (pp % 13) * 2;
            float a0[10], a1[10];
#pragma unroll
            for (int o = 0; o < 10; o++) { a0[o] = 0.f; a1[o] = 0.f; }
#pragma unroll
            for (int u = 0; u < 3; u++)
#pragma unroll
                for (int v = 0; v < 3; v++) {
                    float xv0 = sx[(y + u) * 28 + x0 + v];
                    float xv1 = sx[(y + u) * 28 + x0 + v + 1];
                    const float* wp = &sw[((r * 3 + u) * 3 + v) * 10];
#pragma unroll
                    for (int o = 0; o < 10; o++) {
                        a0[o] = fmaf(xv0, wp[o], a0[o]);
                        a1[o] = fmaf(xv1, wp[o], a1[o]);
                    }
                }
#pragma unroll
            for (int o = 0; o < 10; o++) {
                size_t off = ((((size_t)b * 10 + o) * 4 + r) * 26 + y) * 26 + x0;
                g_buf0[off] = a0[o]; g_buf0[off + 1] = a1[o];
                ts[o] += a0[o] + a1[o];
                tq[o] += a0[o] * a0[o] + a1[o] * a1[o];
            }
        }
    }
#pragma unroll
    for (int o = 0; o < 10; o++) {
        float s = warpsum(ts[o]);
        float q = warpsum(tq[o]);
        if ((tid & 31) == 0) { atomicAdd(&bsum[o], s); atomicAdd(&bsq[o], q); }
    }
    __syncthreads();
    if (tid < 10) {
        atomicAdd(&g_sum[tid], (double)bsum[tid]);
        atomicAdd(&g_sq[tid], (double)bsq[tid]);
    }
}

// ---------------- layer-2 pooled (mean,max) with BN0 inline ----------------
__global__ void __launch_bounds__(256) pool26(const float* __restrict__ in, int B,
                                              const float* __restrict__ bng,
                                              const float* __restrict__ bnb, float invN) {
    const int H2 = 676;
    __shared__ float sc[10], sh[10];
    bn_smem(threadIdx.x, 0, bng, bnb, invN, sc, sh);
    __syncthreads();
    int total = B * 4 * H2;
    for (int idx = blockIdx.x * blockDim.x + threadIdx.x; idx < total;
         idx += gridDim.x * blockDim.x) {
        int pos = idx % H2;
        int s = (idx / H2) & 3;
        int b = idx / (4 * H2);
        const float* p = in + ((size_t)b * 40 + s) * H2 + pos;
        float sum = 0.f, mx = -3.4e38f;
#pragma unroll
        for (int c = 0; c < 10; c++) {
            float v = fmaf(p[(size_t)c * 4 * H2], sc[c], sh[c]);
            v = v > 0.f ? v : 0.f;
            sum += v; mx = fmaxf(mx, v);
        }
        g_pool[((size_t)b * 8 + s) * H2 + pos]     = sum * 0.1f;
        g_pool[((size_t)b * 8 + 4 + s) * H2 + pos] = mx;
    }
}

// ---------------- layer-2 GG attention conv, f32x2 pixel pairs ----------------
__global__ void __launch_bounds__(192) attk2() {
    constexpr int H = 26, H2 = 676, PW4 = 32;
    __shared__ __align__(16) float pt[8 * PW4 * PW4 + 16];
    __shared__ __align__(8) float wd[784];
    int b = blockIdx.x >> 2, r = blockIdx.x & 3, tid = threadIdx.x;
    for (int i = tid; i < 8 * PW4 * PW4 + 16; i += 192) pt[i] = 0.f;
    for (int i = tid; i < 392; i += 192) {
        float w = g_wa[r * 392 + i];
        wd[2 * i] = w; wd[2 * i + 1] = w;
    }
    __syncthreads();
    const float* pb = g_pool + (size_t)b * 8 * H2;
    for (int idx = tid; idx < 8 * H2; idx += 192) {
        int js = idx / H2, pos = idx - js * H2;
        int y = pos / H, x = pos - y * H;
        pt[(js * PW4 + y + 3) * PW4 + x + 3] = pb[idx];
    }
    __syncthreads();
    constexpr int NQA = 7;
    for (int t = tid; t < H * NQA; t += 192) {
        int q = t % NQA, y = t / NQA, x0 = q * 4;
        u64 acc01 = 0ull, acc23 = 0ull;
#pragma unroll
        for (int js = 0; js < 8; js++) {
#pragma unroll
            for (int u = 0; u < 7; u++) {
                const u64* rp = (const u64*)&pt[(js * PW4 + y + u) * PW4 + x0];
                u64 P0 = rp[0], P1 = rp[1], P2 = rp[2], P3 = rp[3], P4 = rp[4];
                float p0l, p0h, p1l, p1h, p2l, p2h, p3l, p3h, p4l, p4h;
                upk2(P0, p0l, p0h); upk2(P1, p1l, p1h); upk2(P2, p2l, p2h);
                upk2(P3, p3l, p3h); upk2(P4, p4l, p4h);
                u64 O0 = pk2(p0h, p1l), O1 = pk2(p1h, p2l), O2 = pk2(p2h, p3l), O3 = pk2(p3h, p4l);
                const u64* wp = (const u64*)&wd[(js * 49 + u * 7) * 2];
                acc01 = ffma2(P0, wp[0], acc01); acc23 = ffma2(P1, wp[0], acc23);
                acc01 = ffma2(O0, wp[1], acc01); acc23 = ffma2(O1, wp[1], acc23);
                acc01 = ffma2(P1, wp[2], acc01); acc23 = ffma2(P2, wp[2], acc23);
                acc01 = ffma2(O1, wp[3], acc01); acc23 = ffma2(O2, wp[3], acc23);
                acc01 = ffma2(P2, wp[4], acc01); acc23 = ffma2(P3, wp[4], acc23);
                acc01 = ffma2(O2, wp[5], acc01); acc23 = ffma2(O3, wp[5], acc23);
                acc01 = ffma2(P3, wp[6], acc01); acc23 = ffma2(P4, wp[6], acc23);
            }
        }
        float a0, a1, a2, a3; upk2(acc01, a0, a1); upk2(acc23, a2, a3);
        float* ob = &g_att[((size_t)b * 4 + r) * H2 + y * H];
        if (x0 < H)     ob[x0]     = 1.f / (1.f + expf(-a0));
        if (x0 + 1 < H) ob[x0 + 1] = 1.f / (1.f + expf(-a1));
        if (x0 + 2 < H) ob[x0 + 2] = 1.f / (1.f + expf(-a2));
        if (x0 + 3 < H) ob[x0 + 3] = 1.f / (1.f + expf(-a3));
    }
}

// ---------------- layer-2 GG conv, y-split x4, BN0 inline, stats1 ----------------
__global__ void __launch_bounds__(160, 2) convL2(const float* __restrict__ in,
                                                 float* __restrict__ out,
                                                 const float* __restrict__ bng,
                                                 const float* __restrict__ bnb, float invN) {
    extern __shared__ float sm[];
    float* sx = sm;            // 40*8*28 = 8960 (+8 pad)
    float* sw = sm + 8968;     // 14400
    __shared__ float bsum[10], bsq[10], sc[10], sh[10];
    int b = blockIdx.x >> 2, yt = blockIdx.x & 3, y0 = yt * 6;
    int tid = threadIdx.x;
    if (tid < 10) { bsum[tid] = 0.f; bsq[tid] = 0.f; }
    bn_smem(tid, 0, bng, bnb, invN, sc, sh);
    if (tid < 8) sx[8960 + tid] = 0.f;
    __syncthreads();
    const float* inb = in + (size_t)b * 27040;
    const float* attp = g_att + (size_t)b * 2704;
    for (int idx = tid; idx < 40 * 8 * 26; idx += 160) {
        int x = idx % 26; int t = idx / 26; int yy = t & 7; int is = t >> 3;
        int gy = y0 + yy;
        float v = inb[is * 676 + gy * 26 + x];
        v = fmaf(v, sc[is >> 2], sh[is >> 2]);
        v = v > 0.f ? v : 0.f;
        v *= __ldg(&attp[(is & 3) * 676 + gy * 26 + x]);
        sx[(is * 8 + yy) * 28 + x] = v;
    }
    {
        const float4* wg = (const float4*)g_wc;
        float4* swv = (float4*)sw;
        for (int i = tid; i < 3600; i += 160) swv[i] = wg[i];
    }
    __syncthreads();

    float ts[10], tq[10];
#pragma unroll
    for (int o = 0; o < 10; o++) { ts[o] = 0.f; tq[o] = 0.f; }

    for (int task = tid; task < 144; task += 160) {
        int q = task % 6;
        int yy = (task / 6) % 6;
        int r = task / 36;
        int x0 = q * 4;
        u64 acc[4][5];
#pragma unroll
        for (int p = 0; p < 4; p++)
#pragma unroll
            for (int k = 0; k < 5; k++) acc[p][k] = 0ull;
        const float* wr = &sw[r * 3600];
        const float* xb0 = &sx[yy * 28 + x0];
        for (int is = 0; is < 40; is++) {
            const float* xb = xb0 + is * 224;
            const float* wb = wr + is * 90;
#pragma unroll
            for (int u = 0; u < 3; u++) {
                float4 v4 = *(const float4*)(xb + u * 28);
                float2 v2 = *(const float2*)(xb + u * 28 + 4);
                u64 xd[6];
                xd[0] = pk2(v4.x, v4.x); xd[1] = pk2(v4.y, v4.y);
                xd[2] = pk2(v4.z, v4.z); xd[3] = pk2(v4.w, v4.w);
                xd[4] = pk2(v2.x, v2.x); xd[5] = pk2(v2.y, v2.y);
#pragma unroll
                for (int v = 0; v < 3; v++) {
                    const u64* wp = (const u64*)(wb + u * 30 + v * 10);
#pragma unroll
                    for (int k = 0; k < 5; k++) {
                        u64 w2 = wp[k];
#pragma unroll
                        for (int p = 0; p < 4; p++)
                            acc[p][k] = ffma2(xd[v + p], w2, acc[p][k]);
                    }
                }
            }
        }
        int y = y0 + yy;
#pragma unroll
        for (int p = 0; p < 4; p++) {
            int x = x0 + p;
#pragma unroll
            for (int k = 0; k < 5; k++) {
                float lo, hi; upk2(acc[p][k], lo, hi);
                ts[2 * k] += lo;     tq[2 * k] += lo * lo;
                ts[2 * k + 1] += hi; tq[2 * k + 1] += hi * hi;
                size_t o0 = ((((size_t)b * 10 + 2 * k) * 4 + r) * 24 + y) * 24 + x;
                out[o0] = lo;
                out[o0 + (size_t)2304] = hi;   // 4*24*24
            }
        }
    }
#pragma unroll
    for (int o = 0; o < 10; o++) {
        float s = warpsum(ts[o]);
        float qv = warpsum(tq[o]);
        if ((tid & 31) == 0) { atomicAdd(&bsum[o], s); atomicAdd(&bsq[o], qv); }
    }
    __syncthreads();
    if (tid < 10) {
        atomicAdd(&g_sum[10 + tid], (double)bsum[tid]);
        atomicAdd(&g_sq[10 + tid], (double)bsq[tid]);
    }
}

// ---------------- BN1 + ReLU + 2x2 pool (24 -> 12) ----------------
__global__ void __launch_bounds__(256) bnpool2(const float* __restrict__ in,
                                               float* __restrict__ out, int B,
                                               const float* __restrict__ bng,
                                               const float* __restrict__ bnb, float invN) {
    __shared__ float sc[10], sh[10];
    bn_smem(threadIdx.x, 1, bng, bnb, invN, sc, sh);
    __syncthreads();
    int total = B * 10 * 4 * 144;
    int idx = blockIdx.x * blockDim.x + threadIdx.x;
    if (idx >= total) return;
    int x = idx % 12, y = (idx / 12) % 12;
    int c = (idx / 576) % 10;
    int bcs = idx / 144;
    const float* p = in + (size_t)bcs * 576 + (2 * y) * 24 + 2 * x;
    float s = sc[c], t = sh[c];
    float v0 = fmaf(p[0], s, t), v1 = fmaf(p[1], s, t);
    float v2 = fmaf(p[24], s, t), v3 = fmaf(p[25], s, t);
    float v = fmaxf(fmaxf(v0, v1), fmaxf(v2, v3));
    out[idx] = v > 0.f ? v : 0.f;
}

// ---------------- fused layer: BN(in)+ReLU -> pool -> att -> gate -> conv -> stats
template <int H, int NT, int PXCH, int GIMG>
__global__ void __launch_bounds__(NT, 2) fusedgg(const float* __restrict__ in,
                                                 float* __restrict__ out,
                                                 int wlayer, int alayer, int statsIdx,
                                                 int bnIdx, const float* __restrict__ bng,
                                                 const float* __restrict__ bnb, float invN) {
    constexpr int HO = H - 2, WO = H - 2, HP = (H + 3) & ~3;
    constexpr int H2 = H * H, PLANE = H * HP;
    constexpr int NQ = (WO + PXCH - 1) / PXCH;
    constexpr int TASKS = GIMG * 4 * HO * NQ;
    constexpr int PW4 = ((H + 6) + 3) & ~3, TILE = 8 * PW4 * PW4;
    constexpr int NQA = (H + 3) / 4;
    extern __shared__ float sm[];
    float* sx = sm;                              // GIMG*40*PLANE (+8 pad)
    float* sw = sm + GIMG * 40 * PLANE + 8;      // 14400; aliased during att phase:
    float* tile = sw;                            //   TILE + 16
    float* wa_s = sw + TILE + 16;                //   1568
    float* att_s = wa_s + 1568;                  //   GIMG*4*H2
    __shared__ float bsum[10], bsq[10], sc[10], sh[10];
    int grp = blockIdx.x, tid = threadIdx.x;
    if (tid < 10) { bsum[tid] = 0.f; bsq[tid] = 0.f; }
    bn_smem(tid, bnIdx, bng, bnb, invN, sc, sh);
    if (tid < 8) sx[GIMG * 40 * PLANE + tid] = 0.f;
    __syncthreads();

    // load input (BN+ReLU, ungated)
    for (int li = 0; li < GIMG; li++) {
        int b = grp * GIMG + li;
        const float* inb = in + (size_t)b * 40 * H2;
        for (int idx = tid; idx < 40 * H2; idx += NT) {
            int is = idx / H2, pos = idx - is * H2;
            int y = pos / H, x = pos - y * H;
            float v = inb[idx];
            v = fmaf(v, sc[is >> 2], sh[is >> 2]);
            v = v > 0.f ? v : 0.f;
            sx[((li * 40 + is) * H + y) * HP + x] = v;
        }
    }
    for (int i = tid; i < 1568; i += NT) wa_s[i] = g_wa[alayer * 1568 + i];
    __syncthreads();

    // per-image pool -> att
    for (int li = 0; li < GIMG; li++) {
        for (int i = tid; i < TILE; i += NT) tile[i] = 0.f;
        __syncthreads();
        for (int idx = tid; idx < 4 * H2; idx += NT) {
            int s = idx / H2, pos = idx - s * H2;
            int y = pos / H, x = pos - y * H;
            float sum = 0.f, mx = -3.4e38f;
#pragma unroll
            for (int c = 0; c < 10; c++) {
                float v = sx[((li * 40 + c * 4 + s) * H + y) * HP + x];
                sum += v; mx = fmaxf(mx, v);
            }
            tile[(s * PW4 + y + 3) * PW4 + x + 3] = sum * 0.1f;
            tile[((4 + s) * PW4 + y + 3) * PW4 + x + 3] = mx;
        }
        __syncthreads();
        for (int t = tid; t < 4 * NQA * H; t += NT) {
            int q = t % NQA; int y = (t / NQA) % H; int r = t / (NQA * H);
            int x0 = q * 4;
            float a0 = 0.f, a1 = 0.f, a2 = 0.f, a3 = 0.f;
            const float* wb0 = &wa_s[r * 392];
#pragma unroll
            for (int js = 0; js < 8; js++) {
#pragma unroll
                for (int u = 0; u < 7; u++) {
                    const float* rowp = &tile[(js * PW4 + y + u) * PW4 + x0];
                    float4 A = *(const float4*)rowp;
                    float4 Bv = *(const float4*)(rowp + 4);
                    float2 Cv = *(const float2*)(rowp + 8);
                    float rr[10] = {A.x, A.y, A.z, A.w, Bv.x, Bv.y, Bv.z, Bv.w, Cv.x, Cv.y};
                    const float* wb = &wb0[js * 49 + u * 7];
#pragma unroll
                    for (int v = 0; v < 7; v++) {
                        float w = wb[v];
                        a0 = fmaf(rr[v], w, a0);
                        a1 = fmaf(rr[v + 1], w, a1);
                        a2 = fmaf(rr[v + 2], w, a2);
                        a3 = fmaf(rr[v + 3], w, a3);
                    }
                }
            }
            float* ob = &att_s[(li * 4 + r) * H2 + y * H];
            if (x0 < H)     ob[x0]     = 1.f / (1.f + expf(-a0));
            if (x0 + 1 < H) ob[x0 + 1] = 1.f / (1.f + expf(-a1));
            if (x0 + 2 < H) ob[x0 + 2] = 1.f / (1.f + expf(-a2));
            if (x0 + 3 < H) ob[x0 + 3] = 1.f / (1.f + expf(-a3));
        }
        __syncthreads();
    }

    // gate in place
    for (int li = 0; li < GIMG; li++)
        for (int idx = tid; idx < 40 * H2; idx += NT) {
            int is = idx / H2, pos = idx - is * H2;
            int y = pos / H, x = pos - y * H;
            sx[((li * 40 + is) * H + y) * HP + x] *= att_s[(li * 4 + (is & 3)) * H2 + pos];
        }
    __syncthreads();
    // conv weights overwrite tile/wa_s/att_s
    {
        const float4* wg = (const float4*)&g_wc[wlayer * 14400];
        float4* swv = (float4*)sw;
        for (int i = tid; i < 3600; i += NT) swv[i] = wg[i];
    }
    __syncthreads();

    float ts[10], tq[10];
#pragma unroll
    for (int o = 0; o < 10; o++) { ts[o] = 0.f; tq[o] = 0.f; }

    for (int task = tid; task < TASKS; task += NT) {
        int q = task % NQ;
        int t2 = task / NQ;
        int y = t2 % HO; t2 /= HO;
        int r = t2 & 3; int li = t2 >> 2;
        int x0 = q * PXCH;
        u64 acc[PXCH][5];
#pragma unroll
        for (int p = 0; p < PXCH; p++)
#pragma unroll
            for (int k = 0; k < 5; k++) acc[p][k] = 0ull;
        const float* wr = &sw[r * 3600];
        const float* xb0 = &sx[(li * 40 * H + y) * HP + x0];
        for (int is = 0; is < 40; is++) {
            const float* xb = xb0 + is * PLANE;
            const float* wb = wr + is * 90;
#pragma unroll
            for (int u = 0; u < 3; u++) {
                u64 xd[PXCH + 2];
                if (PXCH == 4) {
                    float4 v4 = *(const float4*)(xb + u * HP);
                    float2 v2 = *(const float2*)(xb + u * HP + 4);
                    xd[0] = pk2(v4.x, v4.x); xd[1] = pk2(v4.y, v4.y);
                    xd[2] = pk2(v4.z, v4.z); xd[3] = pk2(v4.w, v4.w);
                    xd[4] = pk2(v2.x, v2.x); xd[5] = pk2(v2.y, v2.y);
                } else {
                    float2 vA = *(const float2*)(xb + u * HP);
                    float2 vB = *(const float2*)(xb + u * HP + 2);
                    xd[0] = pk2(vA.x, vA.x); xd[1] = pk2(vA.y, vA.y);
                    xd[2] = pk2(vB.x, vB.x); xd[3] = pk2(vB.y, vB.y);
                }
#pragma unroll
                for (int v = 0; v < 3; v++) {
                    const u64* wp = (const u64*)(wb + u * 30 + v * 10);
#pragma unroll
                    for (int k = 0; k < 5; k++) {
                        u64 w2 = wp[k];
#pragma unroll
                        for (int p = 0; p < PXCH; p++)
                            acc[p][k] = ffma2(xd[v + p], w2, acc[p][k]);
                    }
                }
            }
        }
        int b = grp * GIMG + li;
#pragma unroll
        for (int p = 0; p < PXCH; p++) {
            int x = x0 + p;
            if (x < WO) {
#pragma unroll
                for (int k = 0; k < 5; k++) {
                    float lo, hi; upk2(acc[p][k], lo, hi);
                    ts[2 * k] += lo;     tq[2 * k] += lo * lo;
                    ts[2 * k + 1] += hi; tq[2 * k + 1] += hi * hi;
                    size_t o0 = ((((size_t)b * 10 + 2 * k) * 4 + r) * HO + y) * WO + x;
                    out[o0] = lo;
                    out[o0 + (size_t)4 * HO * WO] = hi;
                }
            }
        }
    }
#pragma unroll
    for (int o = 0; o < 10; o++) {
        float s = warpsum(ts[o]);
        float qv = warpsum(tq[o]);
        if ((tid & 31) == 0) { atomicAdd(&bsum[o], s); atomicAdd(&bsq[o], qv); }
    }
    __syncthreads();
    if (tid < 10) {
        atomicAdd(&g_sum[statsIdx * 10 + tid], (double)bsum[tid]);
        atomicAdd(&g_sq[statsIdx * 10 + tid], (double)bsq[tid]);
    }
}

// ---------------- layer 7 fused: BN5 -> pool -> att -> gate -> conv 4x4 -> rmax
__global__ void __launch_bounds__(64) conv7k(const float* __restrict__ in,
                                             float* __restrict__ outp,
                                             const float* __restrict__ bng,
                                             const float* __restrict__ bnb, float invN) {
    __shared__ float sx[640], yv[40], sc[10], sh[10];
    __shared__ float tile[8 * 12 * 12 + 16];
    __shared__ float wa_s[1568];
    __shared__ float att_s[64];
    int b = blockIdx.x, tid = threadIdx.x;
    bn_smem(tid, 5, bng, bnb, invN, sc, sh);
    for (int i = tid; i < 8 * 144 + 16; i += 64) tile[i] = 0.f;
    for (int i = tid; i < 1568; i += 64) wa_s[i] = g_wa[5 * 1568 + i];
    __syncthreads();
    for (int idx = tid; idx < 640; idx += 64) {
        int c = idx >> 6;
        float v = in[(size_t)b * 640 + idx];
        v = fmaf(v, sc[c], sh[c]);
        sx[idx] = v > 0.f ? v : 0.f;
    }
    __syncthreads();
    if (tid < 64) {
        int s = tid / 16, pos = tid & 15;
        int y = pos >> 2, x = pos & 3;
        float sum = 0.f, mx = -3.4e38f;
#pragma unroll
        for (int c = 0; c < 10; c++) {
            float v = sx[(c * 4 + s) * 16 + pos];
            sum += v; mx = fmaxf(mx, v);
        }
        tile[(s * 12 + y + 3) * 12 + x + 3] = sum * 0.1f;
        tile[((4 + s) * 12 + y + 3) * 12 + x + 3] = mx;
    }
    __syncthreads();
    if (tid < 64) {
        int r = tid / 16, pos = tid & 15;
        int y = pos >> 2, x = pos & 3;
        float acc = 0.f;
        const float* wb0 = &wa_s[r * 392];
#pragma unroll
        for (int js = 0; js < 8; js++)
#pragma unroll
            for (int u = 0; u < 7; u++) {
                const float* rowp = &tile[(js * 12 + y + u) * 12 + x];
                const float* wb = &wb0[js * 49 + u * 7];
#pragma unroll
                for (int v = 0; v < 7; v++) acc = fmaf(rowp[v], wb[v], acc);
            }
        att_s[r * 16 + pos] = 1.f / (1.f + expf(-acc));
    }
    __syncthreads();
    for (int idx = tid; idx < 640; idx += 64) {
        int is = (idx >> 4) & 3;
        sx[idx] *= att_s[is * 16 + (idx & 15)];
    }
    __syncthreads();
    if (tid < 40) {
        int r = tid / 10, o = tid % 10;
        float acc = 0.f;
        for (int is = 0; is < 40; is++) {
#pragma unroll
            for (int t = 0; t < 16; t++)
                acc = fmaf(sx[is * 16 + t], __ldg(&g_wc7[((r * 40 + is) * 16 + t) * 10 + o]), acc);
        }
        yv[r * 10 + o] = acc;
    }
    __syncthreads();
    if (tid < 10) {
        float m = yv[tid];
        for (int r = 1; r < 4; r++) m = fmaxf(m, yv[r * 10 + tid]);
        outp[(size_t)b * 10 + tid] = m;
    }
}

// ---------------- launch ----------------
extern "C" void kernel_launch(void* const* d_in, const int* in_sizes, int n_in,
                              void* d_out, int out_size) {
    const float* x  = (const float*)d_in[0];
    const float* c1 = (const float*)d_in[1];
    const float* a1 = (const float*)d_in[2];
    const float* c2 = (const float*)d_in[3];
    const float* a2 = (const float*)d_in[4];
    const float* c3 = (const float*)d_in[5];
    const float* a3 = (const float*)d_in[6];
    const float* c4 = (const float*)d_in[7];
    const float* a4 = (const float*)d_in[8];
    const float* c5 = (const float*)d_in[9];
    const float* a5 = (const float*)d_in[10];
    const float* c6 = (const float*)d_in[11];
    const float* a6 = (const float*)d_in[12];
    const float* c7 = (const float*)d_in[13];
    const float* a7 = (const float*)d_in[14];
    const float* bn_g[6] = {(const float*)d_in[15], (const float*)d_in[17], (const float*)d_in[19],
                            (const float*)d_in[21], (const float*)d_in[23], (const float*)d_in[25]};
    const float* bn_b[6] = {(const float*)d_in[16], (const float*)d_in[18], (const float*)d_in[20],
                            (const float*)d_in[22], (const float*)d_in[24], (const float*)d_in[26]};
    float* out = (float*)d_out;

    int B = in_sizes[0] / 784;
    if (B > BMAX) B = BMAX;

    float *b0, *b1;
    cudaGetSymbolAddress((void**)&b0, g_buf0);
    cudaGetSymbolAddress((void**)&b1, g_buf1);

    const int SML2 = (8968 + 14400) * 4;
    const int SM3 = (2 * 40 * 12 * 12 + 8 + 14400) * 4;
    const int SM4 = (2 * 40 * 10 * 12 + 8 + 14400) * 4;
    const int SM5 = (4 * 40 * 8 * 8 + 8 + 14400) * 4;
    const int SM6 = (4 * 40 * 6 * 8 + 8 + 14400) * 4;
    cudaFuncSetAttribute((const void*)convL2, cudaFuncAttributeMaxDynamicSharedMemorySize, SML2);
    cudaFuncSetAttribute((const void*)fusedgg<12, 256, 4, 2>, cudaFuncAttributeMaxDynamicSharedMemorySize, SM3);
    cudaFuncSetAttribute((const void*)fusedgg<10, 128, 4, 2>, cudaFuncAttributeMaxDynamicSharedMemorySize, SM4);
    cudaFuncSetAttribute((const void*)fusedgg<8, 288, 2, 4>,  cudaFuncAttributeMaxDynamicSharedMemorySize, SM5);
    cudaFuncSetAttribute((const void*)fusedgg<6, 64, 4, 4>,   cudaFuncAttributeMaxDynamicSharedMemorySize, SM6);

    prepk<<<64, 128>>>(c1, c2, c3, c4, c5, c6, c7, a1, a2, a3, a4, a5, a6, a7);

    att1k<<<B, 256>>>(x);
    conv1k<<<B, 256>>>();

    float invN0 = 1.f / (float)(B * 4 * 676);
    {
        int tp = B * 4 * 676;
        pool26<<<(tp + 255) / 256, 256>>>(b0, B, bn_g[0], bn_b[0], invN0);
        attk2<<<B * 4, 192>>>();
        convL2<<<B * 4, 160, SML2>>>(b0, b1, bn_g[0], bn_b[0], invN0);
        int tot = B * 10 * 4 * 144;
        bnpool2<<<(tot + 255) / 256, 256>>>(b1, b0, B, bn_g[1], bn_b[1], 1.f / (float)(B * 4 * 576));
    }

    fusedgg<12, 256, 4, 2><<<B / 2, 256, SM3>>>(b0, b1, 1, 1, 2, -1, bn_g[0], bn_b[0], 0.f);
    fusedgg<10, 128, 4, 2><<<B / 2, 128, SM4>>>(b1, b0, 2, 2, 3, 2, bn_g[2], bn_b[2], 1.f / (float)(B * 4 * 100));
    fusedgg<8, 288, 2, 4><<<B / 4, 288, SM5>>>(b0, b1, 3, 3, 4, 3, bn_g[3], bn_b[3], 1.f / (float)(B * 4 * 64));
    fusedgg<6, 64, 4, 4><<<B / 4, 64, SM6>>>(b1, b0, 4, 4, 5, 4, bn_g[4], bn_b[4], 1.f / (float)(B * 4 * 36));
    conv7k<<<B, 64>>>(b0, out, bn_g[5], bn_b[5], 1.f / (float)(B * 4 * 16));
}

// round 7
// speedup vs baseline: 2.1063x; 1.0898x over previous
#include <cuda_runtime.h>
#include <cstdint>
#include <math.h>

#define BMAX 2048
__device__ float g_buf0[BMAX * 10 * 4 * 26 * 26];
__device__ float g_buf1[BMAX * 10 * 4 * 24 * 24];
__device__ float g_att [BMAX * 4 * 26 * 26];
__device__ float g_pool[BMAX * 2 * 4 * 26 * 26];

__device__ double g_sum[60], g_sq[60];

__device__ float g_wl[4 * 3 * 3 * 10];
__device__ __align__(16) float g_wc[5 * 4 * 10 * 4 * 3 * 3 * 10];
__device__ float g_wc7[4 * 10 * 4 * 4 * 4 * 10];
__device__ float g_wa1[49];
__device__ float g_wa[6 * 4 * 2 * 4 * 7 * 7];

typedef unsigned long long u64;

__device__ __forceinline__ u64 pk2(float lo, float hi) {
    u64 r; asm("mov.b64 %0,{%1,%2};" : "=l"(r) : "f"(lo), "f"(hi)); return r;
}
__device__ __forceinline__ void upk2(u64 v, float& lo, float& hi) {
    asm("mov.b64 {%0,%1},%2;" : "=f"(lo), "=f"(hi) : "l"(v));
}
__device__ __forceinline__ u64 ffma2(u64 a, u64 b, u64 c) {
    u64 d; asm("fma.rn.f32x2 %0,%1,%2,%3;" : "=l"(d) : "l"(a), "l"(b), "l"(c)); return d;
}

__device__ __forceinline__ void rotmap(int r, int u, int v, int K, int& su, int& sv) {
    switch (r & 3) {
        case 0: su = u;         sv = v;         break;
        case 1: su = v;         sv = K - 1 - u; break;
        case 2: su = K - 1 - u; sv = K - 1 - v; break;
        default: su = K - 1 - v; sv = u;        break;
    }
}

__device__ __forceinline__ float warpsum(float v) {
    for (int o = 16; o > 0; o >>= 1) v += __shfl_down_sync(0xffffffffu, v, o);
    return v;
}

__device__ __forceinline__ void bn_smem(int tid, int bnIdx, const float* bng,
                                        const float* bnb, float invN,
                                        float* sc, float* sh) {
    if (tid < 10) {
        if (bnIdx >= 0) {
            double m = g_sum[bnIdx * 10 + tid] * (double)invN;
            double var = g_sq[bnIdx * 10 + tid] * (double)invN - m * m;
            float rstd = rsqrtf((float)var + 2e-5f);
            float s = bng[tid] * rstd;
            sc[tid] = s; sh[tid] = bnb[tid] - (float)m * s;
        } else { sc[tid] = 1.f; sh[tid] = 0.f; }
    }
}

// ---------------- prep ----------------
__global__ void prepk(const float* c1, const float* c2, const float* c3, const float* c4,
                      const float* c5, const float* c6, const float* c7,
                      const float* a1, const float* a2, const float* a3, const float* a4,
                      const float* a5, const float* a6, const float* a7) {
    int tid = blockIdx.x * blockDim.x + threadIdx.x;
    int nth = gridDim.x * blockDim.x;
    const float* cws[5] = {c2, c3, c4, c5, c6};
    const float* aws[6] = {a2, a3, a4, a5, a6, a7};

    for (int idx = tid; idx < 360; idx += nth) {
        int o = idx % 10, t = idx / 10;
        int v = t % 3; t /= 3; int u = t % 3; int r = t / 3;
        int su, sv; rotmap(r, u, v, 3, su, sv);
        g_wl[idx] = c1[o * 9 + su * 3 + sv];
    }
    for (int idx = tid; idx < 5 * 14400; idx += nth) {
        int o = idx % 10; int t = idx / 10;
        int v = t % 3; t /= 3; int u = t % 3; t /= 3;
        int s = t & 3; t >>= 2; int i = t % 10; t /= 10;
        int r = t & 3; int l = t >> 2;
        int sp = (s - r) & 3; int su, sv; rotmap(r, u, v, 3, su, sv);
        g_wc[idx] = cws[l][((o * 10 + i) * 4 + sp) * 9 + su * 3 + sv];
    }
    for (int idx = tid; idx < 25600; idx += nth) {
        int o = idx % 10; int t = idx / 10;
        int v = t & 3; t >>= 2; int u = t & 3; t >>= 2;
        int s = t & 3; t >>= 2; int i = t % 10; int r = t / 10;
        int sp = (s - r) & 3; int su, sv; rotmap(r, u, v, 4, su, sv);
        g_wc7[idx] = c7[((o * 10 + i) * 4 + sp) * 16 + su * 4 + sv];
    }
    for (int idx = tid; idx < 49; idx += nth) g_wa1[idx] = a1[idx] + a1[49 + idx];
    for (int idx = tid; idx < 6 * 1568; idx += nth) {
        int v = idx % 7; int t = idx / 7;
        int u = t % 7; t /= 7; int s = t & 3; t >>= 2;
        int i = t & 1; t >>= 1; int r = t & 3; int l = t >> 2;
        int sp = (s - r) & 3; int su, sv; rotmap(r, u, v, 7, su, sv);
        g_wa[idx] = aws[l][(i * 4 + sp) * 49 + su * 7 + sv];
    }
    for (int idx = tid; idx < 60; idx += nth) { g_sum[idx] = 0.0; g_sq[idx] = 0.0; }
}

// ---------------- layer 1: attention + gate + lifting conv + stats0 ----------------
__global__ void __launch_bounds__(256) l1k(const float* __restrict__ x) {
    __shared__ float xt[34 * 34];
    __shared__ float sxg[784];
    __shared__ float w[49];
    __shared__ float sw[360];
    __shared__ float bsum[10], bsq[10];
    int b = blockIdx.x, tid = threadIdx.x;
    for (int i = tid; i < 34 * 34; i += 256) xt[i] = 0.f;
    for (int i = tid; i < 49; i += 256) w[i] = g_wa1[i];
    for (int i = tid; i < 360; i += 256) sw[i] = g_wl[i];
    if (tid < 10) { bsum[tid] = 0.f; bsq[tid] = 0.f; }
    __syncthreads();
    for (int i = tid; i < 784; i += 256) {
        int y = i / 28, xx = i % 28;
        xt[(y + 3) * 34 + xx + 3] = x[(size_t)b * 784 + i];
    }
    __syncthreads();
    for (int p = tid; p < 784; p += 256) {
        int y = p / 28, xx = p % 28;
        float acc = 0.f;
#pragma unroll
        for (int u = 0; u < 7; u++)
#pragma unroll
            for (int v = 0; v < 7; v++)
                acc = fmaf(xt[(y + u) * 34 + xx + v], w[u * 7 + v], acc);
        float xv = xt[(y + 3) * 34 + xx + 3];
        sxg[p] = xv * (1.f / (1.f + expf(-acc)));
    }
    __syncthreads();
    float ts[10], tq[10];
#pragma unroll
    for (int o = 0; o < 10; o++) { ts[o] = 0.f; tq[o] = 0.f; }
    for (int r = 0; r < 4; r++) {
        for (int pp = tid; pp < 338; pp += 256) {
            int y = pp / 13, x0 = (pp % 13) * 2;
            float a0[10], a1[10];
#pragma unroll
            for (int o = 0; o < 10; o++) { a0[o] = 0.f; a1[o] = 0.f; }
#pragma unroll
            for (int u = 0; u < 3; u++)
#pragma unroll
                for (int v = 0; v < 3; v++) {
                    float xv0 = sxg[(y + u) * 28 + x0 + v];
                    float xv1 = sxg[(y + u) * 28 + x0 + v + 1];
                    const float* wp = &sw[((r * 3 + u) * 3 + v) * 10];
#pragma unroll
                    for (int o = 0; o < 10; o++) {
                        a0[o] = fmaf(xv0, wp[o], a0[o]);
                        a1[o] = fmaf(xv1, wp[o], a1[o]);
                    }
                }
#pragma unroll
            for (int o = 0; o < 10; o++) {
                size_t off = ((((size_t)b * 10 + o) * 4 + r) * 26 + y) * 26 + x0;
                g_buf0[off] = a0[o]; g_buf0[off + 1] = a1[o];
                ts[o] += a0[o] + a1[o];
                tq[o] += a0[o] * a0[o] + a1[o] * a1[o];
            }
        }
    }
#pragma unroll
    for (int o = 0; o < 10; o++) {
        float s = warpsum(ts[o]);
        float q = warpsum(tq[o]);
        if ((tid & 31) == 0) { atomicAdd(&bsum[o], s); atomicAdd(&bsq[o], q); }
    }
    __syncthreads();
    if (tid < 10) {
        atomicAdd(&g_sum[tid], (double)bsum[tid]);
        atomicAdd(&g_sq[tid], (double)bsq[tid]);
    }
}

// ---------------- layer-2 pooled (mean,max) with BN0 inline ----------------
__global__ void __launch_bounds__(256) pool26(const float* __restrict__ in, int B,
                                              const float* __restrict__ bng,
                                              const float* __restrict__ bnb, float invN) {
    const int H2 = 676;
    __shared__ float sc[10], sh[10];
    bn_smem(threadIdx.x, 0, bng, bnb, invN, sc, sh);
    __syncthreads();
    int total = B * 4 * H2;
    for (int idx = blockIdx.x * blockDim.x + threadIdx.x; idx < total;
         idx += gridDim.x * blockDim.x) {
        int pos = idx % H2;
        int s = (idx / H2) & 3;
        int b = idx / (4 * H2);
        const float* p = in + ((size_t)b * 40 + s) * H2 + pos;
        float sum = 0.f, mx = -3.4e38f;
#pragma unroll
        for (int c = 0; c < 10; c++) {
            float v = fmaf(p[(size_t)c * 4 * H2], sc[c], sh[c]);
            v = v > 0.f ? v : 0.f;
            sum += v; mx = fmaxf(mx, v);
        }
        g_pool[((size_t)b * 8 + s) * H2 + pos]     = sum * 0.1f;
        g_pool[((size_t)b * 8 + 4 + s) * H2 + pos] = mx;
    }
}

// ---------------- layer-2 GG attention conv, f32x2 pixel pairs ----------------
__global__ void __launch_bounds__(192) attk2() {
    constexpr int H = 26, H2 = 676, PW4 = 32;
    __shared__ __align__(16) float pt[8 * PW4 * PW4 + 16];
    __shared__ __align__(8) float wd[784];
    int b = blockIdx.x >> 2, r = blockIdx.x & 3, tid = threadIdx.x;
    for (int i = tid; i < 8 * PW4 * PW4 + 16; i += 192) pt[i] = 0.f;
    for (int i = tid; i < 392; i += 192) {
        float w = g_wa[r * 392 + i];
        wd[2 * i] = w; wd[2 * i + 1] = w;
    }
    __syncthreads();
    const float* pb = g_pool + (size_t)b * 8 * H2;
    for (int idx = tid; idx < 8 * H2; idx += 192) {
        int js = idx / H2, pos = idx - js * H2;
        int y = pos / H, x = pos - y * H;
        pt[(js * PW4 + y + 3) * PW4 + x + 3] = pb[idx];
    }
    __syncthreads();
    constexpr int NQA = 7;
    for (int t = tid; t < H * NQA; t += 192) {
        int q = t % NQA, y = t / NQA, x0 = q * 4;
        u64 acc01 = 0ull, acc23 = 0ull;
#pragma unroll
        for (int js = 0; js < 8; js++) {
#pragma unroll
            for (int u = 0; u < 7; u++) {
                const u64* rp = (const u64*)&pt[(js * PW4 + y + u) * PW4 + x0];
                u64 P0 = rp[0], P1 = rp[1], P2 = rp[2], P3 = rp[3], P4 = rp[4];
                float p0l, p0h, p1l, p1h, p2l, p2h, p3l, p3h, p4l, p4h;
                upk2(P0, p0l, p0h); upk2(P1, p1l, p1h); upk2(P2, p2l, p2h);
                upk2(P3, p3l, p3h); upk2(P4, p4l, p4h);
                u64 O0 = pk2(p0h, p1l), O1 = pk2(p1h, p2l), O2 = pk2(p2h, p3l), O3 = pk2(p3h, p4l);
                const u64* wp = (const u64*)&wd[(js * 49 + u * 7) * 2];
                acc01 = ffma2(P0, wp[0], acc01); acc23 = ffma2(P1, wp[0], acc23);
                acc01 = ffma2(O0, wp[1], acc01); acc23 = ffma2(O1, wp[1], acc23);
                acc01 = ffma2(P1, wp[2], acc01); acc23 = ffma2(P2, wp[2], acc23);
                acc01 = ffma2(O1, wp[3], acc01); acc23 = ffma2(O2, wp[3], acc23);
                acc01 = ffma2(P2, wp[4], acc01); acc23 = ffma2(P3, wp[4], acc23);
                acc01 = ffma2(O2, wp[5], acc01); acc23 = ffma2(O3, wp[5], acc23);
                acc01 = ffma2(P3, wp[6], acc01); acc23 = ffma2(P4, wp[6], acc23);
            }
        }
        float a0, a1, a2, a3; upk2(acc01, a0, a1); upk2(acc23, a2, a3);
        float* ob = &g_att[((size_t)b * 4 + r) * H2 + y * H];
        if (x0 < H)     ob[x0]     = 1.f / (1.f + expf(-a0));
        if (x0 + 1 < H) ob[x0 + 1] = 1.f / (1.f + expf(-a1));
        if (x0 + 2 < H) ob[x0 + 2] = 1.f / (1.f + expf(-a2));
        if (x0 + 3 < H) ob[x0 + 3] = 1.f / (1.f + expf(-a3));
    }
}

// ---------------- layer-2 GG conv, y-split x3, BN0 inline, stats1 ----------------
__global__ void __launch_bounds__(192, 2) convL2(const float* __restrict__ in,
                                                 float* __restrict__ out,
                                                 const float* __restrict__ bng,
                                                 const float* __restrict__ bnb, float invN) {
    extern __shared__ float sm[];
    float* sx = sm;            // 40*10*28 = 11200 (+8 pad)
    float* sw = sm + 11208;    // 14400
    __shared__ float bsum[10], bsq[10], sc[10], sh[10];
    int b = blockIdx.x / 3, yt = blockIdx.x % 3, y0 = yt * 8;
    int tid = threadIdx.x;
    if (tid < 10) { bsum[tid] = 0.f; bsq[tid] = 0.f; }
    bn_smem(tid, 0, bng, bnb, invN, sc, sh);
    if (tid < 8) sx[11200 + tid] = 0.f;
    __syncthreads();
    const float* inb = in + (size_t)b * 27040;
    const float* attp = g_att + (size_t)b * 2704;
    for (int idx = tid; idx < 40 * 10 * 26; idx += 192) {
        int x = idx % 26; int t = idx / 26; int yy = t % 10; int is = t / 10;
        int gy = y0 + yy;
        float v = inb[is * 676 + gy * 26 + x];
        v = fmaf(v, sc[is >> 2], sh[is >> 2]);
        v = v > 0.f ? v : 0.f;
        v *= __ldg(&attp[(is & 3) * 676 + gy * 26 + x]);
        sx[(is * 10 + yy) * 28 + x] = v;
    }
    {
        const float4* wg = (const float4*)g_wc;
        float4* swv = (float4*)sw;
        for (int i = tid; i < 3600; i += 192) swv[i] = wg[i];
    }
    __syncthreads();

    float ts[10], tq[10];
#pragma unroll
    for (int o = 0; o < 10; o++) { ts[o] = 0.f; tq[o] = 0.f; }

    {
        int task = tid;   // 192 tasks == 192 threads
        int q = task % 6;
        int yy = (task / 6) % 8;
        int r = task / 48;
        int x0 = q * 4;
        u64 acc[4][5];
#pragma unroll
        for (int p = 0; p < 4; p++)
#pragma unroll
            for (int k = 0; k < 5; k++) acc[p][k] = 0ull;
        const float* wr = &sw[r * 3600];
        const float* xb0 = &sx[yy * 28 + x0];
        for (int is = 0; is < 40; is++) {
            const float* xb = xb0 + is * 280;
            const float* wb = wr + is * 90;
#pragma unroll
            for (int u = 0; u < 3; u++) {
                float4 v4 = *(const float4*)(xb + u * 28);
                float2 v2 = *(const float2*)(xb + u * 28 + 4);
                u64 xd[6];
                xd[0] = pk2(v4.x, v4.x); xd[1] = pk2(v4.y, v4.y);
                xd[2] = pk2(v4.z, v4.z); xd[3] = pk2(v4.w, v4.w);
                xd[4] = pk2(v2.x, v2.x); xd[5] = pk2(v2.y, v2.y);
#pragma unroll
                for (int v = 0; v < 3; v++) {
                    const u64* wp = (const u64*)(wb + u * 30 + v * 10);
#pragma unroll
                    for (int k = 0; k < 5; k++) {
                        u64 w2 = wp[k];
#pragma unroll
                        for (int p = 0; p < 4; p++)
                            acc[p][k] = ffma2(xd[v + p], w2, acc[p][k]);
                    }
                }
            }
        }
        int y = y0 + yy;
#pragma unroll
        for (int p = 0; p < 4; p++) {
            int x = x0 + p;
#pragma unroll
            for (int k = 0; k < 5; k++) {
                float lo, hi; upk2(acc[p][k], lo, hi);
                ts[2 * k] += lo;     tq[2 * k] += lo * lo;
                ts[2 * k + 1] += hi; tq[2 * k + 1] += hi * hi;
                size_t o0 = ((((size_t)b * 10 + 2 * k) * 4 + r) * 24 + y) * 24 + x;
                out[o0] = lo;
                out[o0 + (size_t)2304] = hi;
            }
        }
    }
#pragma unroll
    for (int o = 0; o < 10; o++) {
        float s = warpsum(ts[o]);
        float qv = warpsum(tq[o]);
        if ((tid & 31) == 0) { atomicAdd(&bsum[o], s); atomicAdd(&bsq[o], qv); }
    }
    __syncthreads();
    if (tid < 10) {
        atomicAdd(&g_sum[10 + tid], (double)bsum[tid]);
        atomicAdd(&g_sq[10 + tid], (double)bsq[tid]);
    }
}

// ---------------- fused layer: [BN(+optional 2x2 pool)] -> pool -> att -> gate -> conv
template <int H, int NT, int PXCH, int GIMG, bool LPOOL>
__global__ void __launch_bounds__(NT, 2) fusedgg(const float* __restrict__ in,
                                                 float* __restrict__ out,
                                                 int wlayer, int alayer, int statsIdx,
                                                 int bnIdx, const float* __restrict__ bng,
                                                 const float* __restrict__ bnb, float invN) {
    constexpr int HO = H - 2, WO = H - 2, HP = (H + 3) & ~3;
    constexpr int H2 = H * H, PLANE = H * HP;
    constexpr int NQ = (WO + PXCH - 1) / PXCH;
    constexpr int TASKS = GIMG * 4 * HO * NQ;
    constexpr int PW4 = ((H + 6) + 3) & ~3, TILE = 8 * PW4 * PW4;
    constexpr int NQA = (H + 3) / 4;
    extern __shared__ float sm[];
    float* sx = sm;
    float* sw = sm + GIMG * 40 * PLANE + 8;
    float* tile = sw;
    float* wa_s = sw + TILE + 16;
    float* att_s = wa_s + 1568;
    __shared__ float bsum[10], bsq[10], sc[10], sh[10];
    int grp = blockIdx.x, tid = threadIdx.x;
    if (tid < 10) { bsum[tid] = 0.f; bsq[tid] = 0.f; }
    bn_smem(tid, bnIdx, bng, bnb, invN, sc, sh);
    if (tid < 8) sx[GIMG * 40 * PLANE + tid] = 0.f;
    __syncthreads();

    for (int li = 0; li < GIMG; li++) {
        int b = grp * GIMG + li;
        if (LPOOL) {
            // in: [b][40][24][24]; BN+ReLU+2x2 maxpool -> H=12
            const float* inb = in + (size_t)b * 40 * 576;
            for (int idx = tid; idx < 40 * H2; idx += NT) {
                int is = idx / H2, pos = idx - is * H2;
                int y = pos / H, x = pos - y * H;
                const float* p = inb + (size_t)is * 576 + (2 * y) * 24 + 2 * x;
                float2 A = *(const float2*)p;
                float2 Bv = *(const float2*)(p + 24);
                float s = sc[is >> 2], t = sh[is >> 2];
                float v0 = fmaf(A.x, s, t), v1 = fmaf(A.y, s, t);
                float v2 = fmaf(Bv.x, s, t), v3 = fmaf(Bv.y, s, t);
                float v = fmaxf(fmaxf(v0, v1), fmaxf(v2, v3));
                v = v > 0.f ? v : 0.f;
                sx[((li * 40 + is) * H + y) * HP + x] = v;
            }
        } else {
            const float* inb = in + (size_t)b * 40 * H2;
            for (int idx = tid; idx < 40 * H2; idx += NT) {
                int is = idx / H2, pos = idx - is * H2;
                int y = pos / H, x = pos - y * H;
                float v = inb[idx];
                v = fmaf(v, sc[is >> 2], sh[is >> 2]);
                v = v > 0.f ? v : 0.f;
                sx[((li * 40 + is) * H + y) * HP + x] = v;
            }
        }
    }
    for (int i = tid; i < 1568; i += NT) wa_s[i] = g_wa[alayer * 1568 + i];
    __syncthreads();

    for (int li = 0; li < GIMG; li++) {
        for (int i = tid; i < TILE; i += NT) tile[i] = 0.f;
        __syncthreads();
        for (int idx = tid; idx < 4 * H2; idx += NT) {
            int s = idx / H2, pos = idx - s * H2;
            int y = pos / H, x = pos - y * H;
            float sum = 0.f, mx = -3.4e38f;
#pragma unroll
            for (int c = 0; c < 10; c++) {
                float v = sx[((li * 40 + c * 4 + s) * H + y) * HP + x];
                sum += v; mx = fmaxf(mx, v);
            }
            tile[(s * PW4 + y + 3) * PW4 + x + 3] = sum * 0.1f;
            tile[((4 + s) * PW4 + y + 3) * PW4 + x + 3] = mx;
        }
        __syncthreads();
        for (int t = tid; t < 4 * NQA * H; t += NT) {
            int q = t % NQA; int y = (t / NQA) % H; int r = t / (NQA * H);
            int x0 = q * 4;
            float a0 = 0.f, a1 = 0.f, a2 = 0.f, a3 = 0.f;
            const float* wb0 = &wa_s[r * 392];
#pragma unroll
            for (int js = 0; js < 8; js++) {
#pragma unroll
                for (int u = 0; u < 7; u++) {
                    const float* rowp = &tile[(js * PW4 + y + u) * PW4 + x0];
                    float4 A = *(const float4*)rowp;
                    float4 Bv = *(const float4*)(rowp + 4);
                    float2 Cv = *(const float2*)(rowp + 8);
                    float rr[10] = {A.x, A.y, A.z, A.w, Bv.x, Bv.y, Bv.z, Bv.w, Cv.x, Cv.y};
                    const float* wb = &wb0[js * 49 + u * 7];
#pragma unroll
                    for (int v = 0; v < 7; v++) {
                        float w = wb[v];
                        a0 = fmaf(rr[v], w, a0);
                        a1 = fmaf(rr[v + 1], w, a1);
                        a2 = fmaf(rr[v + 2], w, a2);
                        a3 = fmaf(rr[v + 3], w, a3);
                    }
                }
            }
            float* ob = &att_s[(li * 4 + r) * H2 + y * H];
            if (x0 < H)     ob[x0]     = 1.f / (1.f + expf(-a0));
            if (x0 + 1 < H) ob[x0 + 1] = 1.f / (1.f + expf(-a1));
            if (x0 + 2 < H) ob[x0 + 2] = 1.f / (1.f + expf(-a2));
            if (x0 + 3 < H) ob[x0 + 3] = 1.f / (1.f + expf(-a3));
        }
        __syncthreads();
    }

    for (int li = 0; li < GIMG; li++)
        for (int idx = tid; idx < 40 * H2; idx += NT) {
            int is = idx / H2, pos = idx - is * H2;
            int y = pos / H, x = pos - y * H;
            sx[((li * 40 + is) * H + y) * HP + x] *= att_s[(li * 4 + (is & 3)) * H2 + pos];
        }
    __syncthreads();
    {
        const float4* wg = (const float4*)&g_wc[wlayer * 14400];
        float4* swv = (float4*)sw;
        for (int i = tid; i < 3600; i += NT) swv[i] = wg[i];
    }
    __syncthreads();

    float ts[10], tq[10];
#pragma unroll
    for (int o = 0; o < 10; o++) { ts[o] = 0.f; tq[o] = 0.f; }

    for (int task = tid; task < TASKS; task += NT) {
        int q = task % NQ;
        int t2 = task / NQ;
        int y = t2 % HO; t2 /= HO;
        int r = t2 & 3; int li = t2 >> 2;
        int x0 = q * PXCH;
        u64 acc[PXCH][5];
#pragma unroll
        for (int p = 0; p < PXCH; p++)
#pragma unroll
            for (int k = 0; k < 5; k++) acc[p][k] = 0ull;
        const float* wr = &sw[r * 3600];
        const float* xb0 = &sx[(li * 40 * H + y) * HP + x0];
        for (int is = 0; is < 40; is++) {
            const float* xb = xb0 + is * PLANE;
            const float* wb = wr + is * 90;
#pragma unroll
            for (int u = 0; u < 3; u++) {
                u64 xd[PXCH + 2];
                if (PXCH == 4) {
                    float4 v4 = *(const float4*)(xb + u * HP);
                    float2 v2 = *(const float2*)(xb + u * HP + 4);
                    xd[0] = pk2(v4.x, v4.x); xd[1] = pk2(v4.y, v4.y);
                    xd[2] = pk2(v4.z, v4.z); xd[3] = pk2(v4.w, v4.w);
                    xd[4] = pk2(v2.x, v2.x); xd[5] = pk2(v2.y, v2.y);
                } else {
                    float2 vA = *(const float2*)(xb + u * HP);
                    float2 vB = *(const float2*)(xb + u * HP + 2);
                    xd[0] = pk2(vA.x, vA.x); xd[1] = pk2(vA.y, vA.y);
                    xd[2] = pk2(vB.x, vB.x); xd[3] = pk2(vB.y, vB.y);
                }
#pragma unroll
                for (int v = 0; v < 3; v++) {
                    const u64* wp = (const u64*)(wb + u * 30 + v * 10);
#pragma unroll
                    for (int k = 0; k < 5; k++) {
                        u64 w2 = wp[k];
#pragma unroll
                        for (int p = 0; p < PXCH; p++)
                            acc[p][k] = ffma2(xd[v + p], w2, acc[p][k]);
                    }
                }
            }
        }
        int b = grp * GIMG + li;
#pragma unroll
        for (int p = 0; p < PXCH; p++) {
            int x = x0 + p;
            if (x < WO) {
#pragma unroll
                for (int k = 0; k < 5; k++) {
                    float lo, hi; upk2(acc[p][k], lo, hi);
                    ts[2 * k] += lo;     tq[2 * k] += lo * lo;
                    ts[2 * k + 1] += hi; tq[2 * k + 1] += hi * hi;
                    size_t o0 = ((((size_t)b * 10 + 2 * k) * 4 + r) * HO + y) * WO + x;
                    out[o0] = lo;
                    out[o0 + (size_t)4 * HO * WO] = hi;
                }
            }
        }
    }
#pragma unroll
    for (int o = 0; o < 10; o++) {
        float s = warpsum(ts[o]);
        float qv = warpsum(tq[o]);
        if ((tid & 31) == 0) { atomicAdd(&bsum[o], s); atomicAdd(&bsq[o], qv); }
    }
    __syncthreads();
    if (tid < 10) {
        atomicAdd(&g_sum[statsIdx * 10 + tid], (double)bsum[tid]);
        atomicAdd(&g_sq[statsIdx * 10 + tid], (double)bsq[tid]);
    }
}

// ---------------- layer 7 fused ----------------
__global__ void __launch_bounds__(64) conv7k(const float* __restrict__ in,
                                             float* __restrict__ outp,
                                             const float* __restrict__ bng,
                                             const float* __restrict__ bnb, float invN) {
    __shared__ float sx[640], yv[40], sc[10], sh[10];
    __shared__ float tile[8 * 12 * 12 + 16];
    __shared__ float wa_s[1568];
    __shared__ float att_s[64];
    int b = blockIdx.x, tid = threadIdx.x;
    bn_smem(tid, 5, bng, bnb, invN, sc, sh);
    for (int i = tid; i < 8 * 144 + 16; i += 64) tile[i] = 0.f;
    for (int i = tid; i < 1568; i += 64) wa_s[i] = g_wa[5 * 1568 + i];
    __syncthreads();
    for (int idx = tid; idx < 640; idx += 64) {
        int c = idx >> 6;
        float v = in[(size_t)b * 640 + idx];
        v = fmaf(v, sc[c], sh[c]);
        sx[idx] = v > 0.f ? v : 0.f;
    }
    __syncthreads();
    if (tid < 64) {
        int s = tid / 16, pos = tid & 15;
        int y = pos >> 2, x = pos & 3;
        float sum = 0.f, mx = -3.4e38f;
#pragma unroll
        for (int c = 0; c < 10; c++) {
            float v = sx[(c * 4 + s) * 16 + pos];
            sum += v; mx = fmaxf(mx, v);
        }
        tile[(s * 12 + y + 3) * 12 + x + 3] = sum * 0.1f;
        tile[((4 + s) * 12 + y + 3) * 12 + x + 3] = mx;
    }
    __syncthreads();
    if (tid < 64) {
        int r = tid / 16, pos = tid & 15;
        int y = pos >> 2, x = pos & 3;
        float acc = 0.f;
        const float* wb0 = &wa_s[r * 392];
#pragma unroll
        for (int js = 0; js < 8; js++)
#pragma unroll
            for (int u = 0; u < 7; u++) {
                const float* rowp = &tile[(js * 12 + y + u) * 12 + x];
                const float* wb = &wb0[js * 49 + u * 7];
#pragma unroll
                for (int v = 0; v < 7; v++) acc = fmaf(rowp[v], wb[v], acc);
            }
        att_s[r * 16 + pos] = 1.f / (1.f + expf(-acc));
    }
    __syncthreads();
    for (int idx = tid; idx < 640; idx += 64) {
        int is = (idx >> 4) & 3;
        sx[idx] *= att_s[is * 16 + (idx & 15)];
    }
    __syncthreads();
    if (tid < 40) {
        int r = tid / 10, o = tid % 10;
        float acc = 0.f;
        for (int is = 0; is < 40; is++) {
#pragma unroll
            for (int t = 0; t < 16; t++)
                acc = fmaf(sx[is * 16 + t], __ldg(&g_wc7[((r * 40 + is) * 16 + t) * 10 + o]), acc);
        }
        yv[r * 10 + o] = acc;
    }
    __syncthreads();
    if (tid < 10) {
        float m = yv[tid];
        for (int r = 1; r < 4; r++) m = fmaxf(m, yv[r * 10 + tid]);
        outp[(size_t)b * 10 + tid] = m;
    }
}

// ---------------- launch ----------------
extern "C" void kernel_launch(void* const* d_in, const int* in_sizes, int n_in,
                              void* d_out, int out_size) {
    const float* x  = (const float*)d_in[0];
    const float* c1 = (const float*)d_in[1];
    const float* a1 = (const float*)d_in[2];
    const float* c2 = (const float*)d_in[3];
    const float* a2 = (const float*)d_in[4];
    const float* c3 = (const float*)d_in[5];
    const float* a3 = (const float*)d_in[6];
    const float* c4 = (const float*)d_in[7];
    const float* a4 = (const float*)d_in[8];
    const float* c5 = (const float*)d_in[9];
    const float* a5 = (const float*)d_in[10];
    const float* c6 = (const float*)d_in[11];
    const float* a6 = (const float*)d_in[12];
    const float* c7 = (const float*)d_in[13];
    const float* a7 = (const float*)d_in[14];
    const float* bn_g[6] = {(const float*)d_in[15], (const float*)d_in[17], (const float*)d_in[19],
                            (const float*)d_in[21], (const float*)d_in[23], (const float*)d_in[25]};
    const float* bn_b[6] = {(const float*)d_in[16], (const float*)d_in[18], (const float*)d_in[20],
                            (const float*)d_in[22], (const float*)d_in[24], (const float*)d_in[26]};
    float* out = (float*)d_out;

    int B = in_sizes[0] / 784;
    if (B > BMAX) B = BMAX;

    float *b0, *b1;
    cudaGetSymbolAddress((void**)&b0, g_buf0);
    cudaGetSymbolAddress((void**)&b1, g_buf1);

    const int SML2 = (11208 + 14400) * 4;
    const int SM3 = (2 * 40 * 12 * 12 + 8 + 14400) * 4;
    const int SM4 = (2 * 40 * 10 * 12 + 8 + 14400) * 4;
    const int SM5 = (4 * 40 * 8 * 8 + 8 + 14400) * 4;
    const int SM6 = (4 * 40 * 6 * 8 + 8 + 14400) * 4;
    cudaFuncSetAttribute((const void*)convL2, cudaFuncAttributeMaxDynamicSharedMemorySize, SML2);
    cudaFuncSetAttribute((const void*)fusedgg<12, 256, 4, 2, true>,  cudaFuncAttributeMaxDynamicSharedMemorySize, SM3);
    cudaFuncSetAttribute((const void*)fusedgg<10, 256, 4, 2, false>, cudaFuncAttributeMaxDynamicSharedMemorySize, SM4);
    cudaFuncSetAttribute((const void*)fusedgg<8, 288, 2, 4, false>,  cudaFuncAttributeMaxDynamicSharedMemorySize, SM5);
    cudaFuncSetAttribute((const void*)fusedgg<6, 128, 4, 4, false>,  cudaFuncAttributeMaxDynamicSharedMemorySize, SM6);

    prepk<<<64, 128>>>(c1, c2, c3, c4, c5, c6, c7, a1, a2, a3, a4, a5, a6, a7);

    l1k<<<B, 256>>>(x);

    float invN0 = 1.f / (float)(B * 4 * 676);
    {
        int tp = B * 4 * 676;
        pool26<<<(tp + 255) / 256, 256>>>(b0, B, bn_g[0], bn_b[0], invN0);
        attk2<<<B * 4, 192>>>();
        convL2<<<B * 3, 192, SML2>>>(b0, b1, bn_g[0], bn_b[0], invN0);
    }

    fusedgg<12, 256, 4, 2, true><<<B / 2, 256, SM3>>>(b1, b0, 1, 1, 2, 1, bn_g[1], bn_b[1], 1.f / (float)(B * 4 * 576));
    fusedgg<10, 256, 4, 2, false><<<B / 2, 256, SM4>>>(b0, b1, 2, 2, 3, 2, bn_g[2], bn_b[2], 1.f / (float)(B * 4 * 100));
    fusedgg<8, 288, 2, 4, false><<<B / 4, 288, SM5>>>(b1, b0, 3, 3, 4, 3, bn_g[3], bn_b[3], 1.f / (float)(B * 4 * 64));
    fusedgg<6, 128, 4, 4, false><<<B / 4, 128, SM6>>>(b0, b1, 4, 4, 5, 4, bn_g[4], bn_b[4], 1.f / (float)(B * 4 * 36));
    conv7k<<<B, 64>>>(b1, out, bn_g[5], bn_b[5], 1.f / (float)(B * 4 * 16));
}